// round 2
// baseline (speedup 1.0000x reference)
#include <cuda_runtime.h>
#include <math.h>

// Problem constants
#define NB      8192
#define TSTEPS  50
#define NM      12          // basis functions per dim
#define NW      10368       // 12*12*6*12  (W in [i0][i1][d][i2] layout)

// Precomputed weights + params (computed per launch by prep kernels; deterministic)
__device__ float g_W[NW];
__device__ float g_prm[9];   // L[3], w1[3]=pi/(2L), invsqrtL[3]

#define PI_D 3.14159265358979323846

// ---------------------------------------------------------------------------
// prep_L: L = 1.5*max|basis| per dim; derived params.  1 block.
// ---------------------------------------------------------------------------
__global__ void prep_L(const float* __restrict__ basis) {
    __shared__ float red[256];
    int tid = threadIdx.x;
    for (int d = 0; d < 3; ++d) {
        float m = 0.f;
        for (int r = tid; r < 256; r += blockDim.x)
            m = fmaxf(m, fabsf(basis[r * 3 + d]));
        red[tid] = m;
        __syncthreads();
        for (int s = blockDim.x / 2; s > 0; s >>= 1) {
            if (tid < s) red[tid] = fmaxf(red[tid], red[tid + s]);
            __syncthreads();
        }
        if (tid == 0) {
            float L = 1.5f * red[0];
            g_prm[d]     = L;
            g_prm[3 + d] = (float)(PI_D) / (2.0f * L);
            g_prm[6 + d] = 1.0f / sqrtf(L);
        }
        __syncthreads();
    }
}

// ---------------------------------------------------------------------------
// prep_W: W[d,m] = beta[d,m] * sqrt_psd[d,m], stored as [i0][i1][d][i2]
// ---------------------------------------------------------------------------
__global__ void prep_W(const float* __restrict__ beta, const float* __restrict__ ls) {
    int idx = blockIdx.x * blockDim.x + threadIdx.x;
    if (idx >= NW) return;
    int i2 = idx % 12;
    int d  = (idx / 12) % 6;
    int i1 = (idx / 72) % 12;
    int i0 = idx / 864;
    int m  = (i0 * 12 + i1) * 12 + i2;

    float ls0 = ls[d * 3 + 0], ls1 = ls[d * 3 + 1], ls2 = ls[d * 3 + 2];
    float w0 = g_prm[3] * (float)(i0 + 1);
    float w1 = g_prm[4] * (float)(i1 + 1);
    float w2 = g_prm[5] * (float)(i2 + 1);
    float e = -0.25f * (w0 * w0 * ls0 * ls0 + w1 * w1 * ls1 * ls1 + w2 * w2 * ls2 * ls2);
    // (2*pi)^(3/4)
    float psd = 3.96850262992049984f * sqrtf(ls0 * ls1 * ls2) * expf(e);
    g_W[idx] = beta[d * 1728 + m] * psd;
}

// ---------------------------------------------------------------------------
// Acceleration:  a^k = -Gamma^k_{ij} v^i v^j  on the HSGP metric.
// Work on the big contraction is split over the 4-lane group via `sub`
// (lane handles i0 in [sub*3, sub*3+3)); partials reduced by shfl_xor.
// ---------------------------------------------------------------------------
__device__ __forceinline__ void accel(
    const float4* __restrict__ Wsm, int sub,
    float L0, float L1, float L2,
    float w10, float w11, float w12,
    float is0, float is1, float is2,
    float px, float py, float pz,
    float vx, float vy, float vz,
    float& ax, float& ay, float& az)
{
    // dim-2 basis values in registers (inner contraction, literal indices)
    float s2r[12], c2r[12];
    // dim-0 / dim-1 (dynamically indexed -> local mem, cheap: few LDL per iter)
    float2 a0[12], a1[12];

    {
        float arg = w10 * (px + L0);
        float sb, cb; sincosf(arg, &sb, &cb);
        float sk = sb, ck = cb;
        #pragma unroll
        for (int k = 0; k < 12; ++k) {
            a0[k] = make_float2(is0 * sk, is0 * ck * (w10 * (float)(k + 1)));
            float ns = sk * cb + ck * sb;
            float nc = ck * cb - sk * sb;
            sk = ns; ck = nc;
        }
    }
    {
        float arg = w11 * (py + L1);
        float sb, cb; sincosf(arg, &sb, &cb);
        float sk = sb, ck = cb;
        #pragma unroll
        for (int k = 0; k < 12; ++k) {
            a1[k] = make_float2(is1 * sk, is1 * ck * (w11 * (float)(k + 1)));
            float ns = sk * cb + ck * sb;
            float nc = ck * cb - sk * sb;
            sk = ns; ck = nc;
        }
    }
    {
        float arg = w12 * (pz + L2);
        float sb, cb; sincosf(arg, &sb, &cb);
        float sk = sb, ck = cb;
        #pragma unroll
        for (int k = 0; k < 12; ++k) {
            s2r[k] = is2 * sk;
            c2r[k] = is2 * ck * (w12 * (float)(k + 1));
            float ns = sk * cb + ck * sb;
            float nc = ck * cb - sk * sb;
            sk = ns; ck = nc;
        }
    }

    float gf[6] = {0,0,0,0,0,0};
    float dA[6] = {0,0,0,0,0,0};   // d/dx0 of gf
    float dB[6] = {0,0,0,0,0,0};   // d/dx1
    float dC[6] = {0,0,0,0,0,0};   // d/dx2

    #pragma unroll 1
    for (int ii = 0; ii < 3; ++ii) {
        int i = sub * 3 + ii;
        float uss[6] = {0,0,0,0,0,0};
        float ucs[6] = {0,0,0,0,0,0};
        float usc[6] = {0,0,0,0,0,0};
        const float4* Wi = Wsm + i * (12 * 18);
        #pragma unroll 2
        for (int j = 0; j < 12; ++j) {
            const float4* __restrict__ Wij = Wi + j * 18;
            float s1j = a1[j].x, c1j = a1[j].y;
            #pragma unroll
            for (int d = 0; d < 6; ++d) {
                float4 wa = Wij[d * 3 + 0];
                float4 wb = Wij[d * 3 + 1];
                float4 wc = Wij[d * 3 + 2];
                float ts, tc;
                ts =      wa.x * s2r[0];
                ts = fmaf(wa.y,  s2r[1],  ts);
                ts = fmaf(wa.z,  s2r[2],  ts);
                ts = fmaf(wa.w,  s2r[3],  ts);
                ts = fmaf(wb.x,  s2r[4],  ts);
                ts = fmaf(wb.y,  s2r[5],  ts);
                ts = fmaf(wb.z,  s2r[6],  ts);
                ts = fmaf(wb.w,  s2r[7],  ts);
                ts = fmaf(wc.x,  s2r[8],  ts);
                ts = fmaf(wc.y,  s2r[9],  ts);
                ts = fmaf(wc.z,  s2r[10], ts);
                ts = fmaf(wc.w,  s2r[11], ts);
                tc =      wa.x * c2r[0];
                tc = fmaf(wa.y,  c2r[1],  tc);
                tc = fmaf(wa.z,  c2r[2],  tc);
                tc = fmaf(wa.w,  c2r[3],  tc);
                tc = fmaf(wb.x,  c2r[4],  tc);
                tc = fmaf(wb.y,  c2r[5],  tc);
                tc = fmaf(wb.z,  c2r[6],  tc);
                tc = fmaf(wb.w,  c2r[7],  tc);
                tc = fmaf(wc.x,  c2r[8],  tc);
                tc = fmaf(wc.y,  c2r[9],  tc);
                tc = fmaf(wc.z,  c2r[10], tc);
                tc = fmaf(wc.w,  c2r[11], tc);
                uss[d] = fmaf(ts, s1j, uss[d]);
                ucs[d] = fmaf(ts, c1j, ucs[d]);
                usc[d] = fmaf(tc, s1j, usc[d]);
            }
        }
        float s0i = a0[i].x, c0i = a0[i].y;
        #pragma unroll
        for (int d = 0; d < 6; ++d) {
            gf[d] = fmaf(uss[d], s0i, gf[d]);
            dA[d] = fmaf(uss[d], c0i, dA[d]);
            dB[d] = fmaf(ucs[d], s0i, dB[d]);
            dC[d] = fmaf(usc[d], s0i, dC[d]);
        }
    }

    // reduce 24 partials across the 4-lane group (all lanes end identical)
    #pragma unroll
    for (int d = 0; d < 6; ++d) {
        gf[d] += __shfl_xor_sync(0xffffffffu, gf[d], 1);
        gf[d] += __shfl_xor_sync(0xffffffffu, gf[d], 2);
        dA[d] += __shfl_xor_sync(0xffffffffu, dA[d], 1);
        dA[d] += __shfl_xor_sync(0xffffffffu, dA[d], 2);
        dB[d] += __shfl_xor_sync(0xffffffffu, dB[d], 1);
        dB[d] += __shfl_xor_sync(0xffffffffu, dB[d], 2);
        dC[d] += __shfl_xor_sync(0xffffffffu, dC[d], 1);
        dC[d] += __shfl_xor_sync(0xffffffffu, dC[d], 2);
    }

    // Metric g = I + sym-fill(gf); inverse by cofactors
    float g00 = gf[0] + 1.f, g01 = gf[1], g11 = gf[2] + 1.f;
    float g02 = gf[3], g12 = gf[4], g22 = gf[5] + 1.f;
    float k00 = g11 * g22 - g12 * g12;
    float k01 = g02 * g12 - g01 * g22;
    float k02 = g01 * g12 - g02 * g11;
    float det = g00 * k00 + g01 * k01 + g02 * k02;
    float idet = 1.0f / det;
    float i00 = k00 * idet, i01 = k01 * idet, i02 = k02 * idet;
    float i11 = (g00 * g22 - g02 * g02) * idet;
    float i12 = (g01 * g02 - g00 * g12) * idet;
    float i22 = (g00 * g11 - g01 * g01) * idet;

    // F[q] = v . d(g_q)/dx   (q = sym index of metric component)
    float F0 = vx * dA[0] + vy * dB[0] + vz * dC[0];
    float F1 = vx * dA[1] + vy * dB[1] + vz * dC[1];
    float F2 = vx * dA[2] + vy * dB[2] + vz * dC[2];
    float F3 = vx * dA[3] + vy * dB[3] + vz * dC[3];
    float F4 = vx * dA[4] + vy * dB[4] + vz * dC[4];
    float F5 = vx * dA[5] + vy * dB[5] + vz * dC[5];
    // A_l = sum_j v_j F[sym(l,j)]
    float A0 = vx * F0 + vy * F1 + vz * F3;
    float A1 = vx * F1 + vy * F2 + vz * F4;
    float A2 = vx * F3 + vy * F4 + vz * F5;
    // B_l = v^T D(:,:,l) v
    float xx = vx * vx, yy = vy * vy, zz = vz * vz;
    float xy = 2.f * vx * vy, xz = 2.f * vx * vz, yz = 2.f * vy * vz;
    float B0 = xx * dA[0] + yy * dA[2] + zz * dA[5] + xy * dA[1] + xz * dA[3] + yz * dA[4];
    float B1 = xx * dB[0] + yy * dB[2] + zz * dB[5] + xy * dB[1] + xz * dB[3] + yz * dB[4];
    float B2 = xx * dC[0] + yy * dC[2] + zz * dC[5] + xy * dC[1] + xz * dC[3] + yz * dC[4];
    float h0 = 2.f * A0 - B0;
    float h1 = 2.f * A1 - B1;
    float h2 = 2.f * A2 - B2;
    ax = -0.5f * (i00 * h0 + i01 * h1 + i02 * h2);
    ay = -0.5f * (i01 * h0 + i11 * h1 + i12 * h2);
    az = -0.5f * (i02 * h0 + i12 * h1 + i22 * h2);
}

// ---------------------------------------------------------------------------
// Main integration kernel.
// Grid 256 x 128 threads; group of 4 lanes per trajectory (8192 groups).
// W (41.5 KB) staged in shared memory once per block.
// ---------------------------------------------------------------------------
__global__ void __launch_bounds__(128)
geo_kernel(const float* __restrict__ pos0, const float* __restrict__ vel0,
           float* __restrict__ out)
{
    __shared__ float4 Wsm[NW / 4];
    {
        const float4* Wg4 = reinterpret_cast<const float4*>(g_W);
        for (int i = threadIdx.x; i < NW / 4; i += 128) Wsm[i] = Wg4[i];
    }
    float L0 = g_prm[0], L1 = g_prm[1], L2 = g_prm[2];
    float w10 = g_prm[3], w11 = g_prm[4], w12 = g_prm[5];
    float is0 = g_prm[6], is1 = g_prm[7], is2 = g_prm[8];
    __syncthreads();

    int gt  = blockIdx.x * 128 + threadIdx.x;
    int b   = gt >> 2;
    int sub = gt & 3;

    float px = pos0[b * 3 + 0], py = pos0[b * 3 + 1], pz = pos0[b * 3 + 2];
    float vx = vel0[b * 3 + 0], vy = vel0[b * 3 + 1], vz = vel0[b * 3 + 2];

    if (sub == 0) {
        float* op = out + (size_t)(0 * 2 + 0) * NB * 3 + b * 3;
        float* ov = out + (size_t)(0 * 2 + 1) * NB * 3 + b * 3;
        op[0] = px; op[1] = py; op[2] = pz;
        ov[0] = vx; ov[1] = vy; ov[2] = vz;
    }

    const float dt  = (float)(1.0 / 49.0);
    const float hdt = (float)(0.5 * (1.0 / 49.0));
    const float dt6 = (float)((1.0 / 49.0) / 6.0);

    #pragma unroll 1
    for (int t = 1; t < TSTEPS; ++t) {
        float pacx = 0, pacy = 0, pacz = 0, vacx = 0, vacy = 0, vacz = 0;
        float dpx = 0, dpy = 0, dpz = 0, dvx = 0, dvy = 0, dvz = 0;
        #pragma unroll 1
        for (int s = 0; s < 4; ++s) {
            float pex, pey, pez, vex, vey, vez;
            if (s == 0) {
                pex = px; pey = py; pez = pz;
                vex = vx; vey = vy; vez = vz;
            } else {
                float cs = (s == 3) ? dt : hdt;
                pex = fmaf(cs, dpx, px); pey = fmaf(cs, dpy, py); pez = fmaf(cs, dpz, pz);
                vex = fmaf(cs, dvx, vx); vey = fmaf(cs, dvy, vy); vez = fmaf(cs, dvz, vz);
            }
            float ax, ay, az;
            accel(Wsm, sub, L0, L1, L2, w10, w11, w12, is0, is1, is2,
                  pex, pey, pez, vex, vey, vez, ax, ay, az);
            dpx = vex; dpy = vey; dpz = vez;
            dvx = ax;  dvy = ay;  dvz = az;
            float w = (s == 0 || s == 3) ? 1.f : 2.f;
            pacx = fmaf(w, dpx, pacx); pacy = fmaf(w, dpy, pacy); pacz = fmaf(w, dpz, pacz);
            vacx = fmaf(w, dvx, vacx); vacy = fmaf(w, dvy, vacy); vacz = fmaf(w, dvz, vacz);
        }
        px = fmaf(dt6, pacx, px); py = fmaf(dt6, pacy, py); pz = fmaf(dt6, pacz, pz);
        vx = fmaf(dt6, vacx, vx); vy = fmaf(dt6, vacy, vy); vz = fmaf(dt6, vacz, vz);

        if (sub == 0) {
            float* op = out + ((size_t)(t * 2 + 0) * NB + b) * 3;
            float* ov = out + ((size_t)(t * 2 + 1) * NB + b) * 3;
            op[0] = px; op[1] = py; op[2] = pz;
            ov[0] = vx; ov[1] = vy; ov[2] = vz;
        }
    }
}

// ---------------------------------------------------------------------------
extern "C" void kernel_launch(void* const* d_in, const int* in_sizes, int n_in,
                              void* d_out, int out_size) {
    const float* pos0  = (const float*)d_in[0];
    const float* vel0  = (const float*)d_in[1];
    const float* beta  = (const float*)d_in[2];
    const float* ls    = (const float*)d_in[3];
    const float* basis = (const float*)d_in[4];
    float* out = (float*)d_out;

    prep_L<<<1, 256>>>(basis);
    prep_W<<<81, 128>>>(beta, ls);       // 81*128 = 10368 entries
    geo_kernel<<<256, 128>>>(pos0, vel0, out);
}

// round 3
// speedup vs baseline: 1.9168x; 1.9168x over previous
#include <cuda_runtime.h>
#include <math.h>

// Problem constants
#define NB      8192
#define TSTEPS  50
#define IW      433                 // ulonglong2 stride per i0 block (12*36 + 1 pad)
#define SMEM_BYTES (12 * IW * 16)   // 83136 B dynamic smem: duplicated W

#define PI_D 3.14159265358979323846

typedef unsigned long long ull;

// ---- packed f32x2 helpers (sm_100a) --------------------------------------
__device__ __forceinline__ ull pack2(float lo, float hi) {
    ull r; asm("mov.b64 %0, {%1, %2};" : "=l"(r) : "f"(lo), "f"(hi)); return r;
}
__device__ __forceinline__ void unpack2(ull v, float& lo, float& hi) {
    asm("mov.b64 {%0, %1}, %2;" : "=f"(lo), "=f"(hi) : "l"(v));
}
__device__ __forceinline__ ull mul2(ull a, ull b) {
    ull r; asm("mul.rn.f32x2 %0, %1, %2;" : "=l"(r) : "l"(a), "l"(b)); return r;
}
__device__ __forceinline__ void fma2(ull& acc, ull a, ull b) {
    asm("fma.rn.f32x2 %0, %1, %2, %0;" : "+l"(acc) : "l"(a), "l"(b));
}

// ---------------------------------------------------------------------------
// Acceleration:  a^k = -Gamma^k_{ij} v^i v^j  on the HSGP metric.
// The i0 contraction is split over the 4-lane group via `sub`
// (lane handles i0 in [sub*3, sub*3+3)); partials reduced by shfl_xor.
// Inner dot products over i2 use packed f32x2 FMA against duplicated weights.
// ---------------------------------------------------------------------------
__device__ __forceinline__ void accel(
    const ulonglong2* __restrict__ Wd, int sub,
    float L0, float L1, float L2,
    float w10, float w11, float w12,
    float is0, float is1, float is2,
    float px, float py, float pz,
    float vx, float vy, float vz,
    float& ax, float& ay, float& az)
{
    ull sc2[12];          // packed (s2, c2) per i2 — literal-indexed, registers
    float2 a0[12], a1[12];

    {
        float arg = w10 * (px + L0);
        float sb, cb; sincosf(arg, &sb, &cb);
        float sk = sb, ck = cb;
        #pragma unroll
        for (int k = 0; k < 12; ++k) {
            a0[k] = make_float2(is0 * sk, is0 * ck * (w10 * (float)(k + 1)));
            float ns = sk * cb + ck * sb;
            float nc = ck * cb - sk * sb;
            sk = ns; ck = nc;
        }
    }
    {
        float arg = w11 * (py + L1);
        float sb, cb; sincosf(arg, &sb, &cb);
        float sk = sb, ck = cb;
        #pragma unroll
        for (int k = 0; k < 12; ++k) {
            a1[k] = make_float2(is1 * sk, is1 * ck * (w11 * (float)(k + 1)));
            float ns = sk * cb + ck * sb;
            float nc = ck * cb - sk * sb;
            sk = ns; ck = nc;
        }
    }
    {
        float arg = w12 * (pz + L2);
        float sb, cb; sincosf(arg, &sb, &cb);
        float sk = sb, ck = cb;
        #pragma unroll
        for (int k = 0; k < 12; ++k) {
            sc2[k] = pack2(is2 * sk, is2 * ck * (w12 * (float)(k + 1)));
            float ns = sk * cb + ck * sb;
            float nc = ck * cb - sk * sb;
            sk = ns; ck = nc;
        }
    }

    float gf[6] = {0,0,0,0,0,0};
    float dA[6] = {0,0,0,0,0,0};   // d/dx0 of gf
    float dB[6] = {0,0,0,0,0,0};   // d/dx1
    float dC[6] = {0,0,0,0,0,0};   // d/dx2

    #pragma unroll 1
    for (int ii = 0; ii < 3; ++ii) {
        int i = sub * 3 + ii;
        float uss[6] = {0,0,0,0,0,0};
        float ucs[6] = {0,0,0,0,0,0};
        float usc[6] = {0,0,0,0,0,0};
        const ulonglong2* __restrict__ Wi = Wd + i * IW;
        #pragma unroll 2
        for (int j = 0; j < 12; ++j) {
            const ulonglong2* __restrict__ Wij = Wi + j * 36;
            float s1j = a1[j].x, c1j = a1[j].y;
            #pragma unroll
            for (int d = 0; d < 6; ++d) {
                const ulonglong2* __restrict__ P = Wij + d * 6;
                ulonglong2 u0 = P[0], u1 = P[1], u2 = P[2];
                ulonglong2 u3 = P[3], u4 = P[4], u5 = P[5];
                ull t = mul2(u0.x, sc2[0]);
                fma2(t, u0.y, sc2[1]);
                fma2(t, u1.x, sc2[2]);
                fma2(t, u1.y, sc2[3]);
                fma2(t, u2.x, sc2[4]);
                fma2(t, u2.y, sc2[5]);
                fma2(t, u3.x, sc2[6]);
                fma2(t, u3.y, sc2[7]);
                fma2(t, u4.x, sc2[8]);
                fma2(t, u4.y, sc2[9]);
                fma2(t, u5.x, sc2[10]);
                fma2(t, u5.y, sc2[11]);
                float ts, tc; unpack2(t, ts, tc);
                uss[d] = fmaf(ts, s1j, uss[d]);
                ucs[d] = fmaf(ts, c1j, ucs[d]);
                usc[d] = fmaf(tc, s1j, usc[d]);
            }
        }
        float s0i = a0[i].x, c0i = a0[i].y;
        #pragma unroll
        for (int d = 0; d < 6; ++d) {
            gf[d] = fmaf(uss[d], s0i, gf[d]);
            dA[d] = fmaf(uss[d], c0i, dA[d]);
            dB[d] = fmaf(ucs[d], s0i, dB[d]);
            dC[d] = fmaf(usc[d], s0i, dC[d]);
        }
    }

    // reduce 24 partials across the 4-lane group (all lanes end identical)
    #pragma unroll
    for (int d = 0; d < 6; ++d) {
        gf[d] += __shfl_xor_sync(0xffffffffu, gf[d], 1);
        gf[d] += __shfl_xor_sync(0xffffffffu, gf[d], 2);
        dA[d] += __shfl_xor_sync(0xffffffffu, dA[d], 1);
        dA[d] += __shfl_xor_sync(0xffffffffu, dA[d], 2);
        dB[d] += __shfl_xor_sync(0xffffffffu, dB[d], 1);
        dB[d] += __shfl_xor_sync(0xffffffffu, dB[d], 2);
        dC[d] += __shfl_xor_sync(0xffffffffu, dC[d], 1);
        dC[d] += __shfl_xor_sync(0xffffffffu, dC[d], 2);
    }

    // Metric g = I + sym-fill(gf); inverse by cofactors
    float g00 = gf[0] + 1.f, g01 = gf[1], g11 = gf[2] + 1.f;
    float g02 = gf[3], g12 = gf[4], g22 = gf[5] + 1.f;
    float k00 = g11 * g22 - g12 * g12;
    float k01 = g02 * g12 - g01 * g22;
    float k02 = g01 * g12 - g02 * g11;
    float det = g00 * k00 + g01 * k01 + g02 * k02;
    float idet = 1.0f / det;
    float i00 = k00 * idet, i01 = k01 * idet, i02 = k02 * idet;
    float i11 = (g00 * g22 - g02 * g02) * idet;
    float i12 = (g01 * g02 - g00 * g12) * idet;
    float i22 = (g00 * g11 - g01 * g01) * idet;

    // F[q] = v . d(g_q)/dx
    float F0 = vx * dA[0] + vy * dB[0] + vz * dC[0];
    float F1 = vx * dA[1] + vy * dB[1] + vz * dC[1];
    float F2 = vx * dA[2] + vy * dB[2] + vz * dC[2];
    float F3 = vx * dA[3] + vy * dB[3] + vz * dC[3];
    float F4 = vx * dA[4] + vy * dB[4] + vz * dC[4];
    float F5 = vx * dA[5] + vy * dB[5] + vz * dC[5];
    float A0 = vx * F0 + vy * F1 + vz * F3;
    float A1 = vx * F1 + vy * F2 + vz * F4;
    float A2 = vx * F3 + vy * F4 + vz * F5;
    float xx = vx * vx, yy = vy * vy, zz = vz * vz;
    float xy = 2.f * vx * vy, xz = 2.f * vx * vz, yz = 2.f * vy * vz;
    float B0 = xx * dA[0] + yy * dA[2] + zz * dA[5] + xy * dA[1] + xz * dA[3] + yz * dA[4];
    float B1 = xx * dB[0] + yy * dB[2] + zz * dB[5] + xy * dB[1] + xz * dB[3] + yz * dB[4];
    float B2 = xx * dC[0] + yy * dC[2] + zz * dC[5] + xy * dC[1] + xz * dC[3] + yz * dC[4];
    float h0 = 2.f * A0 - B0;
    float h1 = 2.f * A1 - B1;
    float h2 = 2.f * A2 - B2;
    ax = -0.5f * (i00 * h0 + i01 * h1 + i02 * h2);
    ay = -0.5f * (i01 * h0 + i11 * h1 + i12 * h2);
    az = -0.5f * (i02 * h0 + i12 * h1 + i22 * h2);
}

// ---------------------------------------------------------------------------
// Fused kernel: per-block prep (L from basis, W duplicated into dyn smem)
// followed by the full RK4 geodesic integration.
// Grid 256 x 128 threads; group of 4 lanes per trajectory (8192 groups).
// ---------------------------------------------------------------------------
__global__ void __launch_bounds__(128)
geo_kernel(const float* __restrict__ pos0, const float* __restrict__ vel0,
           const float* __restrict__ beta, const float* __restrict__ ls,
           const float* __restrict__ basis, float* __restrict__ out)
{
    extern __shared__ ulonglong2 Wd[];
    __shared__ float sprm[9];
    __shared__ float red[12];

    int tid = threadIdx.x;

    // ---- L = 1.5 * max|basis| per dim ----
    {
        float m0 = 0.f, m1 = 0.f, m2 = 0.f;
        for (int r = tid; r < 256; r += 128) {
            m0 = fmaxf(m0, fabsf(basis[r * 3 + 0]));
            m1 = fmaxf(m1, fabsf(basis[r * 3 + 1]));
            m2 = fmaxf(m2, fabsf(basis[r * 3 + 2]));
        }
        #pragma unroll
        for (int o = 16; o > 0; o >>= 1) {
            m0 = fmaxf(m0, __shfl_xor_sync(0xffffffffu, m0, o));
            m1 = fmaxf(m1, __shfl_xor_sync(0xffffffffu, m1, o));
            m2 = fmaxf(m2, __shfl_xor_sync(0xffffffffu, m2, o));
        }
        if ((tid & 31) == 0) {
            int w = tid >> 5;
            red[w * 3 + 0] = m0; red[w * 3 + 1] = m1; red[w * 3 + 2] = m2;
        }
        __syncthreads();
        if (tid == 0) {
            #pragma unroll
            for (int d = 0; d < 3; ++d) {
                float M = fmaxf(fmaxf(red[d], red[3 + d]), fmaxf(red[6 + d], red[9 + d]));
                float L = 1.5f * M;
                sprm[d]     = L;
                sprm[3 + d] = (float)(PI_D) / (2.0f * L);
                sprm[6 + d] = 1.0f / sqrtf(L);
            }
        }
        __syncthreads();
    }
    float L0 = sprm[0], L1 = sprm[1], L2 = sprm[2];
    float w10 = sprm[3], w11 = sprm[4], w12 = sprm[5];
    float is0 = sprm[6], is1 = sprm[7], is2 = sprm[8];

    // ---- W[d,m] = beta * sqrt_psd, duplicated (w,w), padded layout ----
    {
        float* Wf = (float*)Wd;
        for (int idx = tid; idx < 10368; idx += 128) {
            int i2 = idx % 12;
            int d  = (idx / 12) % 6;
            int i1 = (idx / 72) % 12;
            int i0 = idx / 864;
            int m  = (i0 * 12 + i1) * 12 + i2;
            float ls0 = ls[d * 3 + 0], ls1 = ls[d * 3 + 1], ls2 = ls[d * 3 + 2];
            float q0 = w10 * (float)(i0 + 1);
            float q1 = w11 * (float)(i1 + 1);
            float q2 = w12 * (float)(i2 + 1);
            float e = -0.25f * (q0 * q0 * ls0 * ls0 + q1 * q1 * ls1 * ls1 + q2 * q2 * ls2 * ls2);
            float psd = 3.96850262992049984f * sqrtf(ls0 * ls1 * ls2) * expf(e);
            float wv = beta[d * 1728 + m] * psd;
            int fo = i0 * (IW * 4) + (i1 * 6 + d) * 24 + i2 * 2;
            Wf[fo]     = wv;
            Wf[fo + 1] = wv;
        }
    }
    __syncthreads();

    // ---- integrate ----
    int gt  = blockIdx.x * 128 + tid;
    int b   = gt >> 2;
    int sub = gt & 3;

    float px = pos0[b * 3 + 0], py = pos0[b * 3 + 1], pz = pos0[b * 3 + 2];
    float vx = vel0[b * 3 + 0], vy = vel0[b * 3 + 1], vz = vel0[b * 3 + 2];

    if (sub == 0) {
        float* op = out + (size_t)0 * NB * 3 + b * 3;
        float* ov = out + (size_t)1 * NB * 3 + b * 3;
        op[0] = px; op[1] = py; op[2] = pz;
        ov[0] = vx; ov[1] = vy; ov[2] = vz;
    }

    const float dt  = (float)(1.0 / 49.0);
    const float hdt = (float)(0.5 * (1.0 / 49.0));
    const float dt6 = (float)((1.0 / 49.0) / 6.0);

    #pragma unroll 1
    for (int t = 1; t < TSTEPS; ++t) {
        float pacx = 0, pacy = 0, pacz = 0, vacx = 0, vacy = 0, vacz = 0;
        float dpx = 0, dpy = 0, dpz = 0, dvx = 0, dvy = 0, dvz = 0;
        #pragma unroll 1
        for (int s = 0; s < 4; ++s) {
            float pex, pey, pez, vex, vey, vez;
            if (s == 0) {
                pex = px; pey = py; pez = pz;
                vex = vx; vey = vy; vez = vz;
            } else {
                float cs = (s == 3) ? dt : hdt;
                pex = fmaf(cs, dpx, px); pey = fmaf(cs, dpy, py); pez = fmaf(cs, dpz, pz);
                vex = fmaf(cs, dvx, vx); vey = fmaf(cs, dvy, vy); vez = fmaf(cs, dvz, vz);
            }
            float ax, ay, az;
            accel(Wd, sub, L0, L1, L2, w10, w11, w12, is0, is1, is2,
                  pex, pey, pez, vex, vey, vez, ax, ay, az);
            dpx = vex; dpy = vey; dpz = vez;
            dvx = ax;  dvy = ay;  dvz = az;
            float w = (s == 0 || s == 3) ? 1.f : 2.f;
            pacx = fmaf(w, dpx, pacx); pacy = fmaf(w, dpy, pacy); pacz = fmaf(w, dpz, pacz);
            vacx = fmaf(w, dvx, vacx); vacy = fmaf(w, dvy, vacy); vacz = fmaf(w, dvz, vacz);
        }
        px = fmaf(dt6, pacx, px); py = fmaf(dt6, pacy, py); pz = fmaf(dt6, pacz, pz);
        vx = fmaf(dt6, vacx, vx); vy = fmaf(dt6, vacy, vy); vz = fmaf(dt6, vacz, vz);

        if (sub == 0) {
            float* op = out + ((size_t)(t * 2 + 0) * NB + b) * 3;
            float* ov = out + ((size_t)(t * 2 + 1) * NB + b) * 3;
            op[0] = px; op[1] = py; op[2] = pz;
            ov[0] = vx; ov[1] = vy; ov[2] = vz;
        }
    }
}

// ---------------------------------------------------------------------------
extern "C" void kernel_launch(void* const* d_in, const int* in_sizes, int n_in,
                              void* d_out, int out_size) {
    const float* pos0  = (const float*)d_in[0];
    const float* vel0  = (const float*)d_in[1];
    const float* beta  = (const float*)d_in[2];
    const float* ls    = (const float*)d_in[3];
    const float* basis = (const float*)d_in[4];
    float* out = (float*)d_out;

    static int attr_done = 0;
    if (!attr_done) {
        cudaFuncSetAttribute(geo_kernel,
                             cudaFuncAttributeMaxDynamicSharedMemorySize, SMEM_BYTES);
        attr_done = 1;
    }
    geo_kernel<<<256, 128, SMEM_BYTES>>>(pos0, vel0, beta, ls, basis, out);
}

// round 4
// speedup vs baseline: 2.9839x; 1.5567x over previous
#include <cuda_runtime.h>
#include <math.h>

#define NB      8192
#define TSTEPS  50
// smem W layout (floats): addr = i0*868 + i1*72 + d*12 + i2
// (16B segments: i0 stride 217, i1 stride 18, d stride 3 -> 8 sub-lanes land on
//  distinct bank-groups mod 8: {0,4,3,7,6,2,1,5})
#define W_FLOATS (12 * 868)          // 10416 floats = 41664 B dynamic smem

#define PI_D 3.14159265358979323846

typedef unsigned long long ull;

// ---- packed f32x2 helpers (sm_100a) --------------------------------------
__device__ __forceinline__ ull pack2(float lo, float hi) {
    ull r; asm("mov.b64 %0, {%1, %2};" : "=l"(r) : "f"(lo), "f"(hi)); return r;
}
__device__ __forceinline__ float hadd2(ull v) {
    float lo, hi; asm("mov.b64 {%0, %1}, %2;" : "=f"(lo), "=f"(hi) : "l"(v));
    return lo + hi;
}
__device__ __forceinline__ ull mul2(ull a, ull b) {
    ull r; asm("mul.rn.f32x2 %0, %1, %2;" : "=l"(r) : "l"(a), "l"(b)); return r;
}
__device__ __forceinline__ void fma2(ull& acc, ull a, ull b) {
    asm("fma.rn.f32x2 %0, %1, %2, %0;" : "+l"(acc) : "l"(a), "l"(b));
}

// ---------------------------------------------------------------------------
// accel: a^k = -Gamma^k_{ij} v^i v^j on the HSGP metric.
// 8-lane group: lane handles i0 in [i0b,i0b+3), i1 in [i1b,i1b+6).
// Inner i2-contraction uses f32x2 with (i2,i2+1) lane pairing -> weights
// read non-duplicated straight from smem.
// ---------------------------------------------------------------------------
__device__ __forceinline__ void accel(
    const ulonglong2* __restrict__ Wd, int i0b, int i1b,
    float L0, float L1, float L2,
    float w10, float w11, float w12,
    float is0, float is1, float is2,
    float px, float py, float pz,
    float vx, float vy, float vz,
    float& ax, float& ay, float& az)
{
    // ---- dim-2 basis (all 12, packed in i2-pairs) ----
    ull s2p[6], c2p[6];
    {
        float arg = w12 * (pz + L2);
        float sa, ca; sincosf(arg, &sa, &ca);
        float sk = sa, ck = ca, fr = w12;
        #pragma unroll
        for (int h = 0; h < 6; ++h) {
            float sA = is2 * sk, cA = is2 * ck * fr;
            float ns = sk * ca + ck * sa;
            float nc = ck * ca - sk * sa;
            float fr2 = fr + w12;
            float sB = is2 * ns, cB = is2 * nc * fr2;
            s2p[h] = pack2(sA, sB);
            c2p[h] = pack2(cA, cB);
            sk = ns * ca + nc * sa;
            ck = nc * ca - ns * sa;
            fr = fr2 + w12;
        }
    }
    // ---- dim-1 basis (lane's 6 values, register-resident) ----
    float s1[6], c1[6];
    {
        float arg = w11 * (py + L1);
        float sa, ca; sincosf(arg, &sa, &ca);
        float fb = (float)(i1b + 1);
        float sk, ck; sincosf(fb * arg, &sk, &ck);
        float fr = w11 * fb;
        #pragma unroll
        for (int j = 0; j < 6; ++j) {
            s1[j] = is1 * sk;
            c1[j] = is1 * ck * fr;
            float ns = sk * ca + ck * sa;
            float nc = ck * ca - sk * sa;
            sk = ns; ck = nc; fr += w11;
        }
    }
    // ---- dim-0 basis (lane's 3 values) ----
    float s0[3], c0[3];
    {
        float arg = w10 * (px + L0);
        float sa, ca; sincosf(arg, &sa, &ca);
        float fb = (float)(i0b + 1);
        float sk, ck; sincosf(fb * arg, &sk, &ck);
        float fr = w10 * fb;
        #pragma unroll
        for (int ii = 0; ii < 3; ++ii) {
            s0[ii] = is0 * sk;
            c0[ii] = is0 * ck * fr;
            float ns = sk * ca + ck * sa;
            float nc = ck * ca - sk * sa;
            sk = ns; ck = nc; fr += w10;
        }
    }

    float gf[6] = {0,0,0,0,0,0};
    float dA[6] = {0,0,0,0,0,0};
    float dB[6] = {0,0,0,0,0,0};
    float dC[6] = {0,0,0,0,0,0};

    const ulonglong2* __restrict__ Wb = Wd + i1b * 18;

    #pragma unroll
    for (int d = 0; d < 6; ++d) {
        #pragma unroll
        for (int ii = 0; ii < 3; ++ii) {
            const ulonglong2* __restrict__ R = Wb + (i0b + ii) * 217 + d * 3;
            ull uss, ucs, usc;
            #pragma unroll
            for (int j = 0; j < 6; ++j) {
                const ulonglong2* __restrict__ P = R + j * 18;
                ulonglong2 u0 = P[0], u1 = P[1], u2 = P[2];
                ull ts = mul2(u0.x, s2p[0]);
                fma2(ts, u0.y, s2p[1]);
                fma2(ts, u1.x, s2p[2]);
                fma2(ts, u1.y, s2p[3]);
                fma2(ts, u2.x, s2p[4]);
                fma2(ts, u2.y, s2p[5]);
                ull tc = mul2(u0.x, c2p[0]);
                fma2(tc, u0.y, c2p[1]);
                fma2(tc, u1.x, c2p[2]);
                fma2(tc, u1.y, c2p[3]);
                fma2(tc, u2.x, c2p[4]);
                fma2(tc, u2.y, c2p[5]);
                ull ds1 = pack2(s1[j], s1[j]);
                ull dc1 = pack2(c1[j], c1[j]);
                if (j == 0) {
                    uss = mul2(ts, ds1);
                    ucs = mul2(ts, dc1);
                    usc = mul2(tc, ds1);
                } else {
                    fma2(uss, ts, ds1);
                    fma2(ucs, ts, dc1);
                    fma2(usc, tc, ds1);
                }
            }
            float us = hadd2(uss), uc = hadd2(ucs), uq = hadd2(usc);
            gf[d] = fmaf(us, s0[ii], gf[d]);
            dA[d] = fmaf(us, c0[ii], dA[d]);
            dB[d] = fmaf(uc, s0[ii], dB[d]);
            dC[d] = fmaf(uq, s0[ii], dC[d]);
        }
    }

    // reduce 24 partials across the 8-lane group (all lanes end identical)
    #pragma unroll
    for (int d = 0; d < 6; ++d) {
        #pragma unroll
        for (int o = 1; o <= 4; o <<= 1) {
            gf[d] += __shfl_xor_sync(0xffffffffu, gf[d], o);
            dA[d] += __shfl_xor_sync(0xffffffffu, dA[d], o);
            dB[d] += __shfl_xor_sync(0xffffffffu, dB[d], o);
            dC[d] += __shfl_xor_sync(0xffffffffu, dC[d], o);
        }
    }

    // Metric g = I + sym-fill(gf); inverse by cofactors
    float g00 = gf[0] + 1.f, g01 = gf[1], g11 = gf[2] + 1.f;
    float g02 = gf[3], g12 = gf[4], g22 = gf[5] + 1.f;
    float k00 = g11 * g22 - g12 * g12;
    float k01 = g02 * g12 - g01 * g22;
    float k02 = g01 * g12 - g02 * g11;
    float det = g00 * k00 + g01 * k01 + g02 * k02;
    float idet = 1.0f / det;
    float i00 = k00 * idet, i01 = k01 * idet, i02 = k02 * idet;
    float i11 = (g00 * g22 - g02 * g02) * idet;
    float i12 = (g01 * g02 - g00 * g12) * idet;
    float i22 = (g00 * g11 - g01 * g01) * idet;

    float F0 = vx * dA[0] + vy * dB[0] + vz * dC[0];
    float F1 = vx * dA[1] + vy * dB[1] + vz * dC[1];
    float F2 = vx * dA[2] + vy * dB[2] + vz * dC[2];
    float F3 = vx * dA[3] + vy * dB[3] + vz * dC[3];
    float F4 = vx * dA[4] + vy * dB[4] + vz * dC[4];
    float F5 = vx * dA[5] + vy * dB[5] + vz * dC[5];
    float A0 = vx * F0 + vy * F1 + vz * F3;
    float A1 = vx * F1 + vy * F2 + vz * F4;
    float A2 = vx * F3 + vy * F4 + vz * F5;
    float xx = vx * vx, yy = vy * vy, zz = vz * vz;
    float xy = 2.f * vx * vy, xz = 2.f * vx * vz, yz = 2.f * vy * vz;
    float B0 = xx * dA[0] + yy * dA[2] + zz * dA[5] + xy * dA[1] + xz * dA[3] + yz * dA[4];
    float B1 = xx * dB[0] + yy * dB[2] + zz * dB[5] + xy * dB[1] + xz * dB[3] + yz * dB[4];
    float B2 = xx * dC[0] + yy * dC[2] + zz * dC[5] + xy * dC[1] + xz * dC[3] + yz * dC[4];
    float h0 = 2.f * A0 - B0;
    float h1 = 2.f * A1 - B1;
    float h2 = 2.f * A2 - B2;
    ax = -0.5f * (i00 * h0 + i01 * h1 + i02 * h2);
    ay = -0.5f * (i01 * h0 + i11 * h1 + i12 * h2);
    az = -0.5f * (i02 * h0 + i12 * h1 + i22 * h2);
}

// ---------------------------------------------------------------------------
// Fused kernel: per-block prep (L, W into padded smem layout) + RK4 loop.
// 256 blocks x 256 threads; 8-lane group per trajectory (8192 groups).
// ---------------------------------------------------------------------------
__global__ void __launch_bounds__(256, 2)
geo_kernel(const float* __restrict__ pos0, const float* __restrict__ vel0,
           const float* __restrict__ beta, const float* __restrict__ ls,
           const float* __restrict__ basis, float* __restrict__ out)
{
    extern __shared__ ulonglong2 Wd[];
    __shared__ float sprm[9];
    __shared__ float red[24];

    int tid = threadIdx.x;

    // ---- L = 1.5 * max|basis| per dim ----
    {
        float m0 = 0.f, m1 = 0.f, m2 = 0.f;
        if (tid < 256) {
            m0 = fabsf(basis[tid * 3 + 0]);
            m1 = fabsf(basis[tid * 3 + 1]);
            m2 = fabsf(basis[tid * 3 + 2]);
        }
        #pragma unroll
        for (int o = 16; o > 0; o >>= 1) {
            m0 = fmaxf(m0, __shfl_xor_sync(0xffffffffu, m0, o));
            m1 = fmaxf(m1, __shfl_xor_sync(0xffffffffu, m1, o));
            m2 = fmaxf(m2, __shfl_xor_sync(0xffffffffu, m2, o));
        }
        if ((tid & 31) == 0) {
            int w = tid >> 5;
            red[w * 3 + 0] = m0; red[w * 3 + 1] = m1; red[w * 3 + 2] = m2;
        }
        __syncthreads();
        if (tid == 0) {
            #pragma unroll
            for (int d = 0; d < 3; ++d) {
                float M = 0.f;
                #pragma unroll
                for (int w = 0; w < 8; ++w) M = fmaxf(M, red[w * 3 + d]);
                float L = 1.5f * M;
                sprm[d]     = L;
                sprm[3 + d] = (float)(PI_D) / (2.0f * L);
                sprm[6 + d] = 1.0f / sqrtf(L);
            }
        }
        __syncthreads();
    }
    float L0 = sprm[0], L1 = sprm[1], L2 = sprm[2];
    float w10 = sprm[3], w11 = sprm[4], w12 = sprm[5];
    float is0 = sprm[6], is1 = sprm[7], is2 = sprm[8];

    // ---- W into padded smem layout ----
    {
        float* Wf = (float*)Wd;
        for (int idx = tid; idx < 10368; idx += 256) {
            int i2 = idx % 12;
            int d  = (idx / 12) % 6;
            int i1 = (idx / 72) % 12;
            int i0 = idx / 864;
            int m  = (i0 * 12 + i1) * 12 + i2;
            float ls0 = ls[d * 3 + 0], ls1 = ls[d * 3 + 1], ls2 = ls[d * 3 + 2];
            float q0 = w10 * (float)(i0 + 1);
            float q1 = w11 * (float)(i1 + 1);
            float q2 = w12 * (float)(i2 + 1);
            float e = -0.25f * (q0 * q0 * ls0 * ls0 + q1 * q1 * ls1 * ls1 + q2 * q2 * ls2 * ls2);
            float psd = 3.96850262992049984f * sqrtf(ls0 * ls1 * ls2) * expf(e);
            Wf[i0 * 868 + i1 * 72 + d * 12 + i2] = beta[d * 1728 + m] * psd;
        }
    }
    __syncthreads();

    // ---- integrate ----
    int gt  = blockIdx.x * 256 + tid;
    int b   = gt >> 3;
    int sub = tid & 7;
    int i0b = (sub >> 1) * 3;
    int i1b = (sub & 1) * 6;

    float px = pos0[b * 3 + 0], py = pos0[b * 3 + 1], pz = pos0[b * 3 + 2];
    float vx = vel0[b * 3 + 0], vy = vel0[b * 3 + 1], vz = vel0[b * 3 + 2];

    if (sub == 0) {
        float* op = out + (size_t)0 * NB * 3 + b * 3;
        float* ov = out + (size_t)1 * NB * 3 + b * 3;
        op[0] = px; op[1] = py; op[2] = pz;
        ov[0] = vx; ov[1] = vy; ov[2] = vz;
    }

    const float dt  = (float)(1.0 / 49.0);
    const float hdt = (float)(0.5 * (1.0 / 49.0));
    const float dt6 = (float)((1.0 / 49.0) / 6.0);

    #pragma unroll 1
    for (int t = 1; t < TSTEPS; ++t) {
        float pacx = 0, pacy = 0, pacz = 0, vacx = 0, vacy = 0, vacz = 0;
        float dpx = 0, dpy = 0, dpz = 0, dvx = 0, dvy = 0, dvz = 0;
        #pragma unroll 1
        for (int s = 0; s < 4; ++s) {
            float pex, pey, pez, vex, vey, vez;
            if (s == 0) {
                pex = px; pey = py; pez = pz;
                vex = vx; vey = vy; vez = vz;
            } else {
                float cs = (s == 3) ? dt : hdt;
                pex = fmaf(cs, dpx, px); pey = fmaf(cs, dpy, py); pez = fmaf(cs, dpz, pz);
                vex = fmaf(cs, dvx, vx); vey = fmaf(cs, dvy, vy); vez = fmaf(cs, dvz, vz);
            }
            float ax, ay, az;
            accel(Wd, i0b, i1b, L0, L1, L2, w10, w11, w12, is0, is1, is2,
                  pex, pey, pez, vex, vey, vez, ax, ay, az);
            dpx = vex; dpy = vey; dpz = vez;
            dvx = ax;  dvy = ay;  dvz = az;
            float w = (s == 0 || s == 3) ? 1.f : 2.f;
            pacx = fmaf(w, dpx, pacx); pacy = fmaf(w, dpy, pacy); pacz = fmaf(w, dpz, pacz);
            vacx = fmaf(w, dvx, vacx); vacy = fmaf(w, dvy, vacy); vacz = fmaf(w, dvz, vacz);
        }
        px = fmaf(dt6, pacx, px); py = fmaf(dt6, pacy, py); pz = fmaf(dt6, pacz, pz);
        vx = fmaf(dt6, vacx, vx); vy = fmaf(dt6, vacy, vy); vz = fmaf(dt6, vacz, vz);

        if (sub == 0) {
            float* op = out + ((size_t)(t * 2 + 0) * NB + b) * 3;
            float* ov = out + ((size_t)(t * 2 + 1) * NB + b) * 3;
            op[0] = px; op[1] = py; op[2] = pz;
            ov[0] = vx; ov[1] = vy; ov[2] = vz;
        }
    }
}

// ---------------------------------------------------------------------------
extern "C" void kernel_launch(void* const* d_in, const int* in_sizes, int n_in,
                              void* d_out, int out_size) {
    const float* pos0  = (const float*)d_in[0];
    const float* vel0  = (const float*)d_in[1];
    const float* beta  = (const float*)d_in[2];
    const float* ls    = (const float*)d_in[3];
    const float* basis = (const float*)d_in[4];
    float* out = (float*)d_out;

    geo_kernel<<<256, 256, W_FLOATS * 4>>>(pos0, vel0, beta, ls, basis, out);
}

// round 5
// speedup vs baseline: 3.7124x; 1.2442x over previous
#include <cuda_runtime.h>
#include <math.h>

#define NB      8192
#define TSTEPS  50
// smem W layout (floats): addr = i0*868 + i1*72 + d*12 + i2
// 16B segments: i0 stride 217, i1 stride 18, d stride 3 -> 8 sub-lanes hit
// distinct bank-groups mod 8: {0,4,3,7,6,2,1,5}
#define W_FLOATS (12 * 868)          // 41664 B dynamic smem

#define PI_D 3.14159265358979323846

typedef unsigned long long ull;

// ---- packed f32x2 helpers (sm_100a) --------------------------------------
__device__ __forceinline__ ull pack2(float lo, float hi) {
    ull r; asm("mov.b64 %0, {%1, %2};" : "=l"(r) : "f"(lo), "f"(hi)); return r;
}
__device__ __forceinline__ float hadd2(ull v) {
    float lo, hi; asm("mov.b64 {%0, %1}, %2;" : "=f"(lo), "=f"(hi) : "l"(v));
    return lo + hi;
}
__device__ __forceinline__ ull mul2(ull a, ull b) {
    ull r; asm("mul.rn.f32x2 %0, %1, %2;" : "=l"(r) : "l"(a), "l"(b)); return r;
}
__device__ __forceinline__ void fma2(ull& acc, ull a, ull b) {
    asm("fma.rn.f32x2 %0, %1, %2, %0;" : "+l"(acc) : "l"(a), "l"(b));
}

// ---------------------------------------------------------------------------
// accel2: geodesic acceleration for TWO trajectories sharing each weight load.
// 8-lane group: lane covers i0 in [i0b,i0b+3), i1 in [i1b,i1b+6).
// ---------------------------------------------------------------------------
__device__ __forceinline__ void accel2(
    const ulonglong2* __restrict__ Wd, int i0b, int i1b,
    float L0, float L1, float L2,
    float w10, float w11, float w12,
    float is0, float is1, float is2,
    const float pe[2][3], const float ve[2][3],
    float ac[2][3])
{
    ull   s2p[2][6], c2p[2][6];
    float s1[2][6],  c1[2][6];
    float sk0[2], ck0[2], fr0[2], sa0[2], ca0[2];

    #pragma unroll
    for (int t = 0; t < 2; ++t) {
        // dim-2 basis: all 12 packed in (i2, i2+1) pairs
        {
            float arg = w12 * (pe[t][2] + L2);
            float sa, ca; sincosf(arg, &sa, &ca);
            float sk = sa, ck = ca, fr = w12;
            #pragma unroll
            for (int h = 0; h < 6; ++h) {
                float sA = is2 * sk, cA = is2 * ck * fr;
                float ns = sk * ca + ck * sa;
                float nc = ck * ca - sk * sa;
                float fr2 = fr + w12;
                float sB = is2 * ns, cB = is2 * nc * fr2;
                s2p[t][h] = pack2(sA, sB);
                c2p[t][h] = pack2(cA, cB);
                sk = ns * ca + nc * sa;
                ck = nc * ca - ns * sa;
                fr = fr2 + w12;
            }
        }
        // dim-1 basis: lane's 6 values, register-resident
        {
            float arg = w11 * (pe[t][1] + L1);
            float sa, ca; sincosf(arg, &sa, &ca);
            float fb = (float)(i1b + 1);
            float sk, ck; sincosf(fb * arg, &sk, &ck);
            float fr = w11 * fb;
            #pragma unroll
            for (int j = 0; j < 6; ++j) {
                s1[t][j] = is1 * sk;
                c1[t][j] = is1 * ck * fr;
                float ns = sk * ca + ck * sa;
                float nc = ck * ca - sk * sa;
                sk = ns; ck = nc; fr += w11;
            }
        }
        // dim-0 basis: recurrence state (consumed inside the rolled ii loop)
        {
            float arg = w10 * (pe[t][0] + L0);
            float sa, ca; sincosf(arg, &sa, &ca);
            float fb = (float)(i0b + 1);
            float sk, ck; sincosf(fb * arg, &sk, &ck);
            sk0[t] = sk; ck0[t] = ck; fr0[t] = w10 * fb;
            sa0[t] = sa; ca0[t] = ca;
        }
    }

    float gf[2][6], dA[2][6], dB[2][6], dC[2][6];
    #pragma unroll
    for (int t = 0; t < 2; ++t)
        #pragma unroll
        for (int d = 0; d < 6; ++d) { gf[t][d] = 0.f; dA[t][d] = 0.f; dB[t][d] = 0.f; dC[t][d] = 0.f; }

    #pragma unroll 1
    for (int ii = 0; ii < 3; ++ii) {
        float s0v[2], c0v[2];
        #pragma unroll
        for (int t = 0; t < 2; ++t) {
            s0v[t] = is0 * sk0[t];
            c0v[t] = is0 * ck0[t] * fr0[t];
            float ns = sk0[t] * ca0[t] + ck0[t] * sa0[t];
            float nc = ck0[t] * ca0[t] - sk0[t] * sa0[t];
            sk0[t] = ns; ck0[t] = nc; fr0[t] += w10;
        }
        const ulonglong2* __restrict__ Ri = Wd + i1b * 18 + (i0b + ii) * 217;
        #pragma unroll
        for (int d = 0; d < 6; ++d) {
            const ulonglong2* __restrict__ R = Ri + d * 3;
            ull uss[2], ucs[2], usc[2];
            #pragma unroll
            for (int j = 0; j < 6; ++j) {
                const ulonglong2* __restrict__ P = R + j * 18;
                ulonglong2 u0 = P[0], u1 = P[1], u2 = P[2];
                #pragma unroll
                for (int t = 0; t < 2; ++t) {
                    ull ts = mul2(u0.x, s2p[t][0]);
                    fma2(ts, u0.y, s2p[t][1]);
                    fma2(ts, u1.x, s2p[t][2]);
                    fma2(ts, u1.y, s2p[t][3]);
                    fma2(ts, u2.x, s2p[t][4]);
                    fma2(ts, u2.y, s2p[t][5]);
                    ull tc = mul2(u0.x, c2p[t][0]);
                    fma2(tc, u0.y, c2p[t][1]);
                    fma2(tc, u1.x, c2p[t][2]);
                    fma2(tc, u1.y, c2p[t][3]);
                    fma2(tc, u2.x, c2p[t][4]);
                    fma2(tc, u2.y, c2p[t][5]);
                    ull ds1 = pack2(s1[t][j], s1[t][j]);
                    ull dc1 = pack2(c1[t][j], c1[t][j]);
                    if (j == 0) {
                        uss[t] = mul2(ts, ds1);
                        ucs[t] = mul2(ts, dc1);
                        usc[t] = mul2(tc, ds1);
                    } else {
                        fma2(uss[t], ts, ds1);
                        fma2(ucs[t], ts, dc1);
                        fma2(usc[t], tc, ds1);
                    }
                }
            }
            #pragma unroll
            for (int t = 0; t < 2; ++t) {
                float us = hadd2(uss[t]), uc = hadd2(ucs[t]), uq = hadd2(usc[t]);
                gf[t][d] = fmaf(us, s0v[t], gf[t][d]);
                dA[t][d] = fmaf(us, c0v[t], dA[t][d]);
                dB[t][d] = fmaf(uc, s0v[t], dB[t][d]);
                dC[t][d] = fmaf(uq, s0v[t], dC[t][d]);
            }
        }
    }

    // reduce 24 partials per trajectory across the 8-lane group
    #pragma unroll
    for (int t = 0; t < 2; ++t)
        #pragma unroll
        for (int d = 0; d < 6; ++d)
            #pragma unroll
            for (int o = 1; o <= 4; o <<= 1) {
                gf[t][d] += __shfl_xor_sync(0xffffffffu, gf[t][d], o);
                dA[t][d] += __shfl_xor_sync(0xffffffffu, dA[t][d], o);
                dB[t][d] += __shfl_xor_sync(0xffffffffu, dB[t][d], o);
                dC[t][d] += __shfl_xor_sync(0xffffffffu, dC[t][d], o);
            }

    #pragma unroll
    for (int t = 0; t < 2; ++t) {
        float vx = ve[t][0], vy = ve[t][1], vz = ve[t][2];
        float g00 = gf[t][0] + 1.f, g01 = gf[t][1], g11 = gf[t][2] + 1.f;
        float g02 = gf[t][3], g12 = gf[t][4], g22 = gf[t][5] + 1.f;
        float k00 = g11 * g22 - g12 * g12;
        float k01 = g02 * g12 - g01 * g22;
        float k02 = g01 * g12 - g02 * g11;
        float det = g00 * k00 + g01 * k01 + g02 * k02;
        float idet = 1.0f / det;
        float i00 = k00 * idet, i01 = k01 * idet, i02 = k02 * idet;
        float i11 = (g00 * g22 - g02 * g02) * idet;
        float i12 = (g01 * g02 - g00 * g12) * idet;
        float i22 = (g00 * g11 - g01 * g01) * idet;

        float F0 = vx * dA[t][0] + vy * dB[t][0] + vz * dC[t][0];
        float F1 = vx * dA[t][1] + vy * dB[t][1] + vz * dC[t][1];
        float F2 = vx * dA[t][2] + vy * dB[t][2] + vz * dC[t][2];
        float F3 = vx * dA[t][3] + vy * dB[t][3] + vz * dC[t][3];
        float F4 = vx * dA[t][4] + vy * dB[t][4] + vz * dC[t][4];
        float F5 = vx * dA[t][5] + vy * dB[t][5] + vz * dC[t][5];
        float A0 = vx * F0 + vy * F1 + vz * F3;
        float A1 = vx * F1 + vy * F2 + vz * F4;
        float A2 = vx * F3 + vy * F4 + vz * F5;
        float xx = vx * vx, yy = vy * vy, zz = vz * vz;
        float xy = 2.f * vx * vy, xz = 2.f * vx * vz, yz = 2.f * vy * vz;
        float B0 = xx * dA[t][0] + yy * dA[t][2] + zz * dA[t][5] + xy * dA[t][1] + xz * dA[t][3] + yz * dA[t][4];
        float B1 = xx * dB[t][0] + yy * dB[t][2] + zz * dB[t][5] + xy * dB[t][1] + xz * dB[t][3] + yz * dB[t][4];
        float B2 = xx * dC[t][0] + yy * dC[t][2] + zz * dC[t][5] + xy * dC[t][1] + xz * dC[t][3] + yz * dC[t][4];
        float h0 = 2.f * A0 - B0;
        float h1 = 2.f * A1 - B1;
        float h2 = 2.f * A2 - B2;
        ac[t][0] = -0.5f * (i00 * h0 + i01 * h1 + i02 * h2);
        ac[t][1] = -0.5f * (i01 * h0 + i11 * h1 + i12 * h2);
        ac[t][2] = -0.5f * (i02 * h0 + i12 * h1 + i22 * h2);
    }
}

// ---------------------------------------------------------------------------
// Fused kernel: per-block prep (L, W into padded smem) + RK4 for 2 traj/group.
// 256 blocks x 128 threads; 4096 groups x 2 trajectories = 8192.
// ---------------------------------------------------------------------------
__global__ void __launch_bounds__(128)
geo_kernel(const float* __restrict__ pos0, const float* __restrict__ vel0,
           const float* __restrict__ beta, const float* __restrict__ ls,
           const float* __restrict__ basis, float* __restrict__ out)
{
    extern __shared__ ulonglong2 Wd[];
    __shared__ float sprm[9];
    __shared__ float red[12];

    int tid = threadIdx.x;

    // ---- L = 1.5 * max|basis| per dim ----
    {
        float m0 = 0.f, m1 = 0.f, m2 = 0.f;
        for (int r = tid; r < 256; r += 128) {
            m0 = fmaxf(m0, fabsf(basis[r * 3 + 0]));
            m1 = fmaxf(m1, fabsf(basis[r * 3 + 1]));
            m2 = fmaxf(m2, fabsf(basis[r * 3 + 2]));
        }
        #pragma unroll
        for (int o = 16; o > 0; o >>= 1) {
            m0 = fmaxf(m0, __shfl_xor_sync(0xffffffffu, m0, o));
            m1 = fmaxf(m1, __shfl_xor_sync(0xffffffffu, m1, o));
            m2 = fmaxf(m2, __shfl_xor_sync(0xffffffffu, m2, o));
        }
        if ((tid & 31) == 0) {
            int w = tid >> 5;
            red[w * 3 + 0] = m0; red[w * 3 + 1] = m1; red[w * 3 + 2] = m2;
        }
        __syncthreads();
        if (tid == 0) {
            #pragma unroll
            for (int d = 0; d < 3; ++d) {
                float M = fmaxf(fmaxf(red[d], red[3 + d]), fmaxf(red[6 + d], red[9 + d]));
                float L = 1.5f * M;
                sprm[d]     = L;
                sprm[3 + d] = (float)(PI_D) / (2.0f * L);
                sprm[6 + d] = 1.0f / sqrtf(L);
            }
        }
        __syncthreads();
    }
    float L0 = sprm[0], L1 = sprm[1], L2 = sprm[2];
    float w10 = sprm[3], w11 = sprm[4], w12 = sprm[5];
    float is0 = sprm[6], is1 = sprm[7], is2 = sprm[8];

    // ---- W into padded smem layout ----
    {
        float* Wf = (float*)Wd;
        for (int idx = tid; idx < 10368; idx += 128) {
            int i2 = idx % 12;
            int d  = (idx / 12) % 6;
            int i1 = (idx / 72) % 12;
            int i0 = idx / 864;
            int m  = (i0 * 12 + i1) * 12 + i2;
            float ls0 = ls[d * 3 + 0], ls1 = ls[d * 3 + 1], ls2 = ls[d * 3 + 2];
            float q0 = w10 * (float)(i0 + 1);
            float q1 = w11 * (float)(i1 + 1);
            float q2 = w12 * (float)(i2 + 1);
            float e = -0.25f * (q0 * q0 * ls0 * ls0 + q1 * q1 * ls1 * ls1 + q2 * q2 * ls2 * ls2);
            float psd = 3.96850262992049984f * sqrtf(ls0 * ls1 * ls2) * expf(e);
            Wf[i0 * 868 + i1 * 72 + d * 12 + i2] = beta[d * 1728 + m] * psd;
        }
    }
    __syncthreads();

    // ---- integrate: 2 trajectories per 8-lane group ----
    int gt    = blockIdx.x * 128 + tid;
    int group = gt >> 3;
    int sub   = tid & 7;
    int i0b   = (sub >> 1) * 3;
    int i1b   = (sub & 1) * 6;

    float p[2][3], v[2][3];
    #pragma unroll
    for (int t = 0; t < 2; ++t) {
        int b = group * 2 + t;
        p[t][0] = pos0[b * 3 + 0]; p[t][1] = pos0[b * 3 + 1]; p[t][2] = pos0[b * 3 + 2];
        v[t][0] = vel0[b * 3 + 0]; v[t][1] = vel0[b * 3 + 1]; v[t][2] = vel0[b * 3 + 2];
    }

    if (sub == 0) {
        #pragma unroll
        for (int t = 0; t < 2; ++t) {
            int b = group * 2 + t;
            float* op = out + (size_t)0 * NB * 3 + b * 3;
            float* ov = out + (size_t)1 * NB * 3 + b * 3;
            op[0] = p[t][0]; op[1] = p[t][1]; op[2] = p[t][2];
            ov[0] = v[t][0]; ov[1] = v[t][1]; ov[2] = v[t][2];
        }
    }

    const float dt  = (float)(1.0 / 49.0);
    const float hdt = (float)(0.5 * (1.0 / 49.0));
    const float dt6 = (float)((1.0 / 49.0) / 6.0);

    #pragma unroll 1
    for (int ts = 1; ts < TSTEPS; ++ts) {
        float pac[2][3], vac[2][3], dp[2][3], dv[2][3];
        #pragma unroll
        for (int t = 0; t < 2; ++t)
            #pragma unroll
            for (int c = 0; c < 3; ++c) {
                pac[t][c] = 0.f; vac[t][c] = 0.f; dp[t][c] = 0.f; dv[t][c] = 0.f;
            }
        #pragma unroll 1
        for (int s = 0; s < 4; ++s) {
            float pe[2][3], ve[2][3], ac[2][3];
            float cs = (s == 3) ? dt : hdt;
            #pragma unroll
            for (int t = 0; t < 2; ++t)
                #pragma unroll
                for (int c = 0; c < 3; ++c) {
                    if (s == 0) { pe[t][c] = p[t][c]; ve[t][c] = v[t][c]; }
                    else {
                        pe[t][c] = fmaf(cs, dp[t][c], p[t][c]);
                        ve[t][c] = fmaf(cs, dv[t][c], v[t][c]);
                    }
                }
            accel2(Wd, i0b, i1b, L0, L1, L2, w10, w11, w12, is0, is1, is2,
                   pe, ve, ac);
            float w = (s == 0 || s == 3) ? 1.f : 2.f;
            #pragma unroll
            for (int t = 0; t < 2; ++t)
                #pragma unroll
                for (int c = 0; c < 3; ++c) {
                    dp[t][c] = ve[t][c]; dv[t][c] = ac[t][c];
                    pac[t][c] = fmaf(w, dp[t][c], pac[t][c]);
                    vac[t][c] = fmaf(w, dv[t][c], vac[t][c]);
                }
        }
        #pragma unroll
        for (int t = 0; t < 2; ++t)
            #pragma unroll
            for (int c = 0; c < 3; ++c) {
                p[t][c] = fmaf(dt6, pac[t][c], p[t][c]);
                v[t][c] = fmaf(dt6, vac[t][c], v[t][c]);
            }

        if (sub == 0) {
            #pragma unroll
            for (int t = 0; t < 2; ++t) {
                int b = group * 2 + t;
                float* op = out + ((size_t)(ts * 2 + 0) * NB + b) * 3;
                float* ov = out + ((size_t)(ts * 2 + 1) * NB + b) * 3;
                op[0] = p[t][0]; op[1] = p[t][1]; op[2] = p[t][2];
                ov[0] = v[t][0]; ov[1] = v[t][1]; ov[2] = v[t][2];
            }
        }
    }
}

// ---------------------------------------------------------------------------
extern "C" void kernel_launch(void* const* d_in, const int* in_sizes, int n_in,
                              void* d_out, int out_size) {
    const float* pos0  = (const float*)d_in[0];
    const float* vel0  = (const float*)d_in[1];
    const float* beta  = (const float*)d_in[2];
    const float* ls    = (const float*)d_in[3];
    const float* basis = (const float*)d_in[4];
    float* out = (float*)d_out;

    geo_kernel<<<256, 128, W_FLOATS * 4>>>(pos0, vel0, beta, ls, basis, out);
}

// round 6
// speedup vs baseline: 3.7725x; 1.0162x over previous
#include <cuda_runtime.h>
#include <math.h>

#define NB      8192
#define TSTEPS  50
// smem W layout (floats): addr = i0*868 + i1*72 + d*12 + i2
// 16B segments: i0 stride 217, i1 stride 18, d stride 3 -> 8 sub-lanes hit
// distinct bank-groups mod 8: {0,4,3,7,6,2,1,5}
#define W_FLOATS (12 * 868)          // 41664 B dynamic smem

#define PI_D 3.14159265358979323846

typedef unsigned long long ull;

// ---- packed f32x2 helpers (sm_100a) --------------------------------------
__device__ __forceinline__ ull pack2(float lo, float hi) {
    ull r; asm("mov.b64 %0, {%1, %2};" : "=l"(r) : "f"(lo), "f"(hi)); return r;
}
__device__ __forceinline__ float hadd2(ull v) {
    float lo, hi; asm("mov.b64 {%0, %1}, %2;" : "=f"(lo), "=f"(hi) : "l"(v));
    return lo + hi;
}
__device__ __forceinline__ ull mul2(ull a, ull b) {
    ull r; asm("mul.rn.f32x2 %0, %1, %2;" : "=l"(r) : "l"(a), "l"(b)); return r;
}
__device__ __forceinline__ ull add2(ull a, ull b) {
    ull r; asm("add.rn.f32x2 %0, %1, %2;" : "=l"(r) : "l"(a), "l"(b)); return r;
}
__device__ __forceinline__ void fma2(ull& acc, ull a, ull b) {
    asm("fma.rn.f32x2 %0, %1, %2, %0;" : "+l"(acc) : "l"(a), "l"(b));
}

// ---------------------------------------------------------------------------
// accel2: geodesic acceleration for TWO trajectories sharing each weight load.
// 8-lane group: lane covers i0 in [i0b,i0b+3), i1 in [i1b,i1b+6).
// Per-lane partials are projected to (gf[6], h[3]) BEFORE the 8-lane shfl
// reduction (linear in the d-arrays), shrinking the reduction 24 -> 9 values.
// ---------------------------------------------------------------------------
__device__ __forceinline__ void accel2(
    const ulonglong2* __restrict__ Wd, int i0b, int i1b,
    float L0, float L1, float L2,
    float w10, float w11, float w12,
    float is0, float is1, float is2,
    const float pe[2][3], const float ve[2][3],
    float ac[2][3])
{
    ull   s2p[2][6], c2p[2][6];
    float s1[2][6],  c1[2][6];
    float sk0[2], ck0[2], fr0[2], sa0[2], ca0[2];

    #pragma unroll
    for (int t = 0; t < 2; ++t) {
        // dim-2 basis: all 12 packed in (i2, i2+1) pairs
        {
            float arg = w12 * (pe[t][2] + L2);
            float sa, ca; __sincosf(arg, &sa, &ca);
            float sk = sa, ck = ca, fr = w12;
            #pragma unroll
            for (int h = 0; h < 6; ++h) {
                float sA = is2 * sk, cA = is2 * ck * fr;
                float ns = sk * ca + ck * sa;
                float nc = ck * ca - sk * sa;
                float fr2 = fr + w12;
                float sB = is2 * ns, cB = is2 * nc * fr2;
                s2p[t][h] = pack2(sA, sB);
                c2p[t][h] = pack2(cA, cB);
                sk = ns * ca + nc * sa;
                ck = nc * ca - ns * sa;
                fr = fr2 + w12;
            }
        }
        // dim-1 basis: lane's 6 values, register-resident
        {
            float arg = w11 * (pe[t][1] + L1);
            float sa, ca; __sincosf(arg, &sa, &ca);
            float fb = (float)(i1b + 1);
            float sk, ck; __sincosf(fb * arg, &sk, &ck);
            float fr = w11 * fb;
            #pragma unroll
            for (int j = 0; j < 6; ++j) {
                s1[t][j] = is1 * sk;
                c1[t][j] = is1 * ck * fr;
                float ns = sk * ca + ck * sa;
                float nc = ck * ca - sk * sa;
                sk = ns; ck = nc; fr += w11;
            }
        }
        // dim-0 basis: recurrence state (consumed inside the rolled ii loop)
        {
            float arg = w10 * (pe[t][0] + L0);
            float sa, ca; __sincosf(arg, &sa, &ca);
            float fb = (float)(i0b + 1);
            float sk, ck; __sincosf(fb * arg, &sk, &ck);
            sk0[t] = sk; ck0[t] = ck; fr0[t] = w10 * fb;
            sa0[t] = sa; ca0[t] = ca;
        }
    }

    float gf[2][6], dA[2][6], dB[2][6], dC[2][6];
    #pragma unroll
    for (int t = 0; t < 2; ++t)
        #pragma unroll
        for (int d = 0; d < 6; ++d) { gf[t][d] = 0.f; dA[t][d] = 0.f; dB[t][d] = 0.f; dC[t][d] = 0.f; }

    #pragma unroll 1
    for (int ii = 0; ii < 3; ++ii) {
        float s0v[2], c0v[2];
        #pragma unroll
        for (int t = 0; t < 2; ++t) {
            s0v[t] = is0 * sk0[t];
            c0v[t] = is0 * ck0[t] * fr0[t];
            float ns = sk0[t] * ca0[t] + ck0[t] * sa0[t];
            float nc = ck0[t] * ca0[t] - sk0[t] * sa0[t];
            sk0[t] = ns; ck0[t] = nc; fr0[t] += w10;
        }
        const ulonglong2* __restrict__ Ri = Wd + i1b * 18 + (i0b + ii) * 217;
        #pragma unroll
        for (int d = 0; d < 6; ++d) {
            const ulonglong2* __restrict__ R = Ri + d * 3;
            ull uss[2], ucs[2], usc[2];
            #pragma unroll
            for (int j = 0; j < 6; ++j) {
                const ulonglong2* __restrict__ P = R + j * 18;
                ulonglong2 u0 = P[0], u1 = P[1], u2 = P[2];
                #pragma unroll
                for (int t = 0; t < 2; ++t) {
                    // 3+3 split chains for shorter critical path
                    ull tsa = mul2(u0.x, s2p[t][0]);
                    fma2(tsa, u0.y, s2p[t][1]);
                    fma2(tsa, u1.x, s2p[t][2]);
                    ull tsb = mul2(u1.y, s2p[t][3]);
                    fma2(tsb, u2.x, s2p[t][4]);
                    fma2(tsb, u2.y, s2p[t][5]);
                    ull ts = add2(tsa, tsb);
                    ull tca = mul2(u0.x, c2p[t][0]);
                    fma2(tca, u0.y, c2p[t][1]);
                    fma2(tca, u1.x, c2p[t][2]);
                    ull tcb = mul2(u1.y, c2p[t][3]);
                    fma2(tcb, u2.x, c2p[t][4]);
                    fma2(tcb, u2.y, c2p[t][5]);
                    ull tc = add2(tca, tcb);
                    ull ds1 = pack2(s1[t][j], s1[t][j]);
                    ull dc1 = pack2(c1[t][j], c1[t][j]);
                    if (j == 0) {
                        uss[t] = mul2(ts, ds1);
                        ucs[t] = mul2(ts, dc1);
                        usc[t] = mul2(tc, ds1);
                    } else {
                        fma2(uss[t], ts, ds1);
                        fma2(ucs[t], ts, dc1);
                        fma2(usc[t], tc, ds1);
                    }
                }
            }
            #pragma unroll
            for (int t = 0; t < 2; ++t) {
                float us = hadd2(uss[t]), uc = hadd2(ucs[t]), uq = hadd2(usc[t]);
                gf[t][d] = fmaf(us, s0v[t], gf[t][d]);
                dA[t][d] = fmaf(us, c0v[t], dA[t][d]);
                dB[t][d] = fmaf(uc, s0v[t], dB[t][d]);
                dC[t][d] = fmaf(uq, s0v[t], dC[t][d]);
            }
        }
    }

    // ---- per-lane projection to h[3] (linear in dA/dB/dC) ----
    float hv[2][3];
    #pragma unroll
    for (int t = 0; t < 2; ++t) {
        float vx = ve[t][0], vy = ve[t][1], vz = ve[t][2];
        float F0 = vx * dA[t][0] + vy * dB[t][0] + vz * dC[t][0];
        float F1 = vx * dA[t][1] + vy * dB[t][1] + vz * dC[t][1];
        float F2 = vx * dA[t][2] + vy * dB[t][2] + vz * dC[t][2];
        float F3 = vx * dA[t][3] + vy * dB[t][3] + vz * dC[t][3];
        float F4 = vx * dA[t][4] + vy * dB[t][4] + vz * dC[t][4];
        float F5 = vx * dA[t][5] + vy * dB[t][5] + vz * dC[t][5];
        float A0 = vx * F0 + vy * F1 + vz * F3;
        float A1 = vx * F1 + vy * F2 + vz * F4;
        float A2 = vx * F3 + vy * F4 + vz * F5;
        float xx = vx * vx, yy = vy * vy, zz = vz * vz;
        float xy = 2.f * vx * vy, xz = 2.f * vx * vz, yz = 2.f * vy * vz;
        float B0 = xx * dA[t][0] + yy * dA[t][2] + zz * dA[t][5] + xy * dA[t][1] + xz * dA[t][3] + yz * dA[t][4];
        float B1 = xx * dB[t][0] + yy * dB[t][2] + zz * dB[t][5] + xy * dB[t][1] + xz * dB[t][3] + yz * dB[t][4];
        float B2 = xx * dC[t][0] + yy * dC[t][2] + zz * dC[t][5] + xy * dC[t][1] + xz * dC[t][3] + yz * dC[t][4];
        hv[t][0] = 2.f * A0 - B0;
        hv[t][1] = 2.f * A1 - B1;
        hv[t][2] = 2.f * A2 - B2;
    }

    // ---- reduce 9 values per trajectory across the 8-lane group ----
    #pragma unroll
    for (int t = 0; t < 2; ++t)
        #pragma unroll
        for (int o = 1; o <= 4; o <<= 1) {
            #pragma unroll
            for (int d = 0; d < 6; ++d)
                gf[t][d] += __shfl_xor_sync(0xffffffffu, gf[t][d], o);
            #pragma unroll
            for (int c = 0; c < 3; ++c)
                hv[t][c] += __shfl_xor_sync(0xffffffffu, hv[t][c], o);
        }

    #pragma unroll
    for (int t = 0; t < 2; ++t) {
        float g00 = gf[t][0] + 1.f, g01 = gf[t][1], g11 = gf[t][2] + 1.f;
        float g02 = gf[t][3], g12 = gf[t][4], g22 = gf[t][5] + 1.f;
        float k00 = g11 * g22 - g12 * g12;
        float k01 = g02 * g12 - g01 * g22;
        float k02 = g01 * g12 - g02 * g11;
        float det = g00 * k00 + g01 * k01 + g02 * k02;
        float idet = 1.0f / det;
        float i00 = k00 * idet, i01 = k01 * idet, i02 = k02 * idet;
        float i11 = (g00 * g22 - g02 * g02) * idet;
        float i12 = (g01 * g02 - g00 * g12) * idet;
        float i22 = (g00 * g11 - g01 * g01) * idet;
        float h0 = hv[t][0], h1 = hv[t][1], h2 = hv[t][2];
        ac[t][0] = -0.5f * (i00 * h0 + i01 * h1 + i02 * h2);
        ac[t][1] = -0.5f * (i01 * h0 + i11 * h1 + i12 * h2);
        ac[t][2] = -0.5f * (i02 * h0 + i12 * h1 + i22 * h2);
    }
}

// ---------------------------------------------------------------------------
// Fused kernel: per-block prep (L, W into padded smem) + RK4 for 2 traj/group.
// 256 blocks x 128 threads; 4096 groups x 2 trajectories = 8192.
// ---------------------------------------------------------------------------
__global__ void __launch_bounds__(128)
geo_kernel(const float* __restrict__ pos0, const float* __restrict__ vel0,
           const float* __restrict__ beta, const float* __restrict__ ls,
           const float* __restrict__ basis, float* __restrict__ out)
{
    extern __shared__ ulonglong2 Wd[];
    __shared__ float sprm[9];
    __shared__ float red[12];

    int tid = threadIdx.x;

    // ---- L = 1.5 * max|basis| per dim ----
    {
        float m0 = 0.f, m1 = 0.f, m2 = 0.f;
        for (int r = tid; r < 256; r += 128) {
            m0 = fmaxf(m0, fabsf(basis[r * 3 + 0]));
            m1 = fmaxf(m1, fabsf(basis[r * 3 + 1]));
            m2 = fmaxf(m2, fabsf(basis[r * 3 + 2]));
        }
        #pragma unroll
        for (int o = 16; o > 0; o >>= 1) {
            m0 = fmaxf(m0, __shfl_xor_sync(0xffffffffu, m0, o));
            m1 = fmaxf(m1, __shfl_xor_sync(0xffffffffu, m1, o));
            m2 = fmaxf(m2, __shfl_xor_sync(0xffffffffu, m2, o));
        }
        if ((tid & 31) == 0) {
            int w = tid >> 5;
            red[w * 3 + 0] = m0; red[w * 3 + 1] = m1; red[w * 3 + 2] = m2;
        }
        __syncthreads();
        if (tid == 0) {
            #pragma unroll
            for (int d = 0; d < 3; ++d) {
                float M = fmaxf(fmaxf(red[d], red[3 + d]), fmaxf(red[6 + d], red[9 + d]));
                float L = 1.5f * M;
                sprm[d]     = L;
                sprm[3 + d] = (float)(PI_D) / (2.0f * L);
                sprm[6 + d] = 1.0f / sqrtf(L);
            }
        }
        __syncthreads();
    }
    float L0 = sprm[0], L1 = sprm[1], L2 = sprm[2];
    float w10 = sprm[3], w11 = sprm[4], w12 = sprm[5];
    float is0 = sprm[6], is1 = sprm[7], is2 = sprm[8];

    // ---- W into padded smem layout (precise math: W feeds everything) ----
    {
        float* Wf = (float*)Wd;
        for (int idx = tid; idx < 10368; idx += 128) {
            int i2 = idx % 12;
            int d  = (idx / 12) % 6;
            int i1 = (idx / 72) % 12;
            int i0 = idx / 864;
            int m  = (i0 * 12 + i1) * 12 + i2;
            float ls0 = ls[d * 3 + 0], ls1 = ls[d * 3 + 1], ls2 = ls[d * 3 + 2];
            float q0 = w10 * (float)(i0 + 1);
            float q1 = w11 * (float)(i1 + 1);
            float q2 = w12 * (float)(i2 + 1);
            float e = -0.25f * (q0 * q0 * ls0 * ls0 + q1 * q1 * ls1 * ls1 + q2 * q2 * ls2 * ls2);
            float psd = 3.96850262992049984f * sqrtf(ls0 * ls1 * ls2) * expf(e);
            Wf[i0 * 868 + i1 * 72 + d * 12 + i2] = beta[d * 1728 + m] * psd;
        }
    }
    __syncthreads();

    // ---- integrate: 2 trajectories per 8-lane group ----
    int gt    = blockIdx.x * 128 + tid;
    int group = gt >> 3;
    int sub   = tid & 7;
    int i0b   = (sub >> 1) * 3;
    int i1b   = (sub & 1) * 6;

    float p[2][3], v[2][3];
    #pragma unroll
    for (int t = 0; t < 2; ++t) {
        int b = group * 2 + t;
        p[t][0] = pos0[b * 3 + 0]; p[t][1] = pos0[b * 3 + 1]; p[t][2] = pos0[b * 3 + 2];
        v[t][0] = vel0[b * 3 + 0]; v[t][1] = vel0[b * 3 + 1]; v[t][2] = vel0[b * 3 + 2];
    }

    if (sub == 0) {
        #pragma unroll
        for (int t = 0; t < 2; ++t) {
            int b = group * 2 + t;
            float* op = out + (size_t)0 * NB * 3 + b * 3;
            float* ov = out + (size_t)1 * NB * 3 + b * 3;
            op[0] = p[t][0]; op[1] = p[t][1]; op[2] = p[t][2];
            ov[0] = v[t][0]; ov[1] = v[t][1]; ov[2] = v[t][2];
        }
    }

    const float dt  = (float)(1.0 / 49.0);
    const float hdt = (float)(0.5 * (1.0 / 49.0));
    const float dt6 = (float)((1.0 / 49.0) / 6.0);

    #pragma unroll 1
    for (int ts = 1; ts < TSTEPS; ++ts) {
        float pac[2][3], vac[2][3], dp[2][3], dv[2][3];
        #pragma unroll
        for (int t = 0; t < 2; ++t)
            #pragma unroll
            for (int c = 0; c < 3; ++c) {
                pac[t][c] = 0.f; vac[t][c] = 0.f; dp[t][c] = 0.f; dv[t][c] = 0.f;
            }
        #pragma unroll 1
        for (int s = 0; s < 4; ++s) {
            float pe[2][3], ve[2][3], ac[2][3];
            float cs = (s == 3) ? dt : hdt;
            #pragma unroll
            for (int t = 0; t < 2; ++t)
                #pragma unroll
                for (int c = 0; c < 3; ++c) {
                    if (s == 0) { pe[t][c] = p[t][c]; ve[t][c] = v[t][c]; }
                    else {
                        pe[t][c] = fmaf(cs, dp[t][c], p[t][c]);
                        ve[t][c] = fmaf(cs, dv[t][c], v[t][c]);
                    }
                }
            accel2(Wd, i0b, i1b, L0, L1, L2, w10, w11, w12, is0, is1, is2,
                   pe, ve, ac);
            float w = (s == 0 || s == 3) ? 1.f : 2.f;
            #pragma unroll
            for (int t = 0; t < 2; ++t)
                #pragma unroll
                for (int c = 0; c < 3; ++c) {
                    dp[t][c] = ve[t][c]; dv[t][c] = ac[t][c];
                    pac[t][c] = fmaf(w, dp[t][c], pac[t][c]);
                    vac[t][c] = fmaf(w, dv[t][c], vac[t][c]);
                }
        }
        #pragma unroll
        for (int t = 0; t < 2; ++t)
            #pragma unroll
            for (int c = 0; c < 3; ++c) {
                p[t][c] = fmaf(dt6, pac[t][c], p[t][c]);
                v[t][c] = fmaf(dt6, vac[t][c], v[t][c]);
            }

        if (sub == 0) {
            #pragma unroll
            for (int t = 0; t < 2; ++t) {
                int b = group * 2 + t;
                float* op = out + ((size_t)(ts * 2 + 0) * NB + b) * 3;
                float* ov = out + ((size_t)(ts * 2 + 1) * NB + b) * 3;
                op[0] = p[t][0]; op[1] = p[t][1]; op[2] = p[t][2];
                ov[0] = v[t][0]; ov[1] = v[t][1]; ov[2] = v[t][2];
            }
        }
    }
}

// ---------------------------------------------------------------------------
extern "C" void kernel_launch(void* const* d_in, const int* in_sizes, int n_in,
                              void* d_out, int out_size) {
    const float* pos0  = (const float*)d_in[0];
    const float* vel0  = (const float*)d_in[1];
    const float* beta  = (const float*)d_in[2];
    const float* ls    = (const float*)d_in[3];
    const float* basis = (const float*)d_in[4];
    float* out = (float*)d_out;

    geo_kernel<<<256, 128, W_FLOATS * 4>>>(pos0, vel0, beta, ls, basis, out);
}

// round 7
// speedup vs baseline: 3.7791x; 1.0018x over previous
#include <cuda_runtime.h>
#include <math.h>

#define NB      8192
#define TSTEPS  50
#define NGROUP  4096
#define NBLK    296          // 2 * 148 SMs -> all blocks resident, balanced
// smem W layout (floats): addr = i0*868 + i1*72 + d*12 + i2
// 16B segments: i0 stride 217, i1 stride 18, d stride 3 -> 8 sub-lanes hit
// distinct bank-groups mod 8: {0,4,3,7,6,2,1,5}
#define W_FLOATS (12 * 868)          // 41664 B dynamic smem

#define PI_D 3.14159265358979323846

typedef unsigned long long ull;

// ---- packed f32x2 helpers (sm_100a) --------------------------------------
__device__ __forceinline__ ull pack2(float lo, float hi) {
    ull r; asm("mov.b64 %0, {%1, %2};" : "=l"(r) : "f"(lo), "f"(hi)); return r;
}
__device__ __forceinline__ float hadd2(ull v) {
    float lo, hi; asm("mov.b64 {%0, %1}, %2;" : "=f"(lo), "=f"(hi) : "l"(v));
    return lo + hi;
}
__device__ __forceinline__ ull mul2(ull a, ull b) {
    ull r; asm("mul.rn.f32x2 %0, %1, %2;" : "=l"(r) : "l"(a), "l"(b)); return r;
}
__device__ __forceinline__ ull add2(ull a, ull b) {
    ull r; asm("add.rn.f32x2 %0, %1, %2;" : "=l"(r) : "l"(a), "l"(b)); return r;
}
__device__ __forceinline__ void fma2(ull& acc, ull a, ull b) {
    asm("fma.rn.f32x2 %0, %1, %2, %0;" : "+l"(acc) : "l"(a), "l"(b));
}

// ---------------------------------------------------------------------------
// accel2: geodesic acceleration for TWO trajectories sharing each weight load.
// 8-lane group: lane covers i0 in [i0b,i0b+3), i1 in [i1b,i1b+6).
// Per-lane partials projected to (gf[6], h[3]) before the masked 8-lane shfl
// reduction.
// ---------------------------------------------------------------------------
__device__ __forceinline__ void accel2(
    const ulonglong2* __restrict__ Wd, int i0b, int i1b, unsigned gmask,
    float L0, float L1, float L2,
    float w10, float w11, float w12,
    float is0, float is1, float is2,
    const float pe[2][3], const float ve[2][3],
    float ac[2][3])
{
    ull   s2p[2][6], c2p[2][6];
    float s1[2][6],  c1[2][6];
    float sk0[2], ck0[2], fr0[2], sa0[2], ca0[2];

    #pragma unroll
    for (int t = 0; t < 2; ++t) {
        // dim-2 basis: all 12 packed in (i2, i2+1) pairs
        {
            float arg = w12 * (pe[t][2] + L2);
            float sa, ca; __sincosf(arg, &sa, &ca);
            float sk = sa, ck = ca, fr = w12;
            #pragma unroll
            for (int h = 0; h < 6; ++h) {
                float sA = is2 * sk, cA = is2 * ck * fr;
                float ns = sk * ca + ck * sa;
                float nc = ck * ca - sk * sa;
                float fr2 = fr + w12;
                float sB = is2 * ns, cB = is2 * nc * fr2;
                s2p[t][h] = pack2(sA, sB);
                c2p[t][h] = pack2(cA, cB);
                sk = ns * ca + nc * sa;
                ck = nc * ca - ns * sa;
                fr = fr2 + w12;
            }
        }
        // dim-1 basis: lane's 6 values, register-resident
        {
            float arg = w11 * (pe[t][1] + L1);
            float sa, ca; __sincosf(arg, &sa, &ca);
            float fb = (float)(i1b + 1);
            float sk, ck; __sincosf(fb * arg, &sk, &ck);
            float fr = w11 * fb;
            #pragma unroll
            for (int j = 0; j < 6; ++j) {
                s1[t][j] = is1 * sk;
                c1[t][j] = is1 * ck * fr;
                float ns = sk * ca + ck * sa;
                float nc = ck * ca - sk * sa;
                sk = ns; ck = nc; fr += w11;
            }
        }
        // dim-0 basis: recurrence state (consumed inside the rolled ii loop)
        {
            float arg = w10 * (pe[t][0] + L0);
            float sa, ca; __sincosf(arg, &sa, &ca);
            float fb = (float)(i0b + 1);
            float sk, ck; __sincosf(fb * arg, &sk, &ck);
            sk0[t] = sk; ck0[t] = ck; fr0[t] = w10 * fb;
            sa0[t] = sa; ca0[t] = ca;
        }
    }

    float gf[2][6], dA[2][6], dB[2][6], dC[2][6];
    #pragma unroll
    for (int t = 0; t < 2; ++t)
        #pragma unroll
        for (int d = 0; d < 6; ++d) { gf[t][d] = 0.f; dA[t][d] = 0.f; dB[t][d] = 0.f; dC[t][d] = 0.f; }

    #pragma unroll 1
    for (int ii = 0; ii < 3; ++ii) {
        float s0v[2], c0v[2];
        #pragma unroll
        for (int t = 0; t < 2; ++t) {
            s0v[t] = is0 * sk0[t];
            c0v[t] = is0 * ck0[t] * fr0[t];
            float ns = sk0[t] * ca0[t] + ck0[t] * sa0[t];
            float nc = ck0[t] * ca0[t] - sk0[t] * sa0[t];
            sk0[t] = ns; ck0[t] = nc; fr0[t] += w10;
        }
        const ulonglong2* __restrict__ Ri = Wd + i1b * 18 + (i0b + ii) * 217;
        #pragma unroll
        for (int d = 0; d < 6; ++d) {
            const ulonglong2* __restrict__ R = Ri + d * 3;
            ull uss[2], ucs[2], usc[2];
            #pragma unroll
            for (int j = 0; j < 6; ++j) {
                const ulonglong2* __restrict__ P = R + j * 18;
                ulonglong2 u0 = P[0], u1 = P[1], u2 = P[2];
                #pragma unroll
                for (int t = 0; t < 2; ++t) {
                    // 3+3 split chains for shorter critical path
                    ull tsa = mul2(u0.x, s2p[t][0]);
                    fma2(tsa, u0.y, s2p[t][1]);
                    fma2(tsa, u1.x, s2p[t][2]);
                    ull tsb = mul2(u1.y, s2p[t][3]);
                    fma2(tsb, u2.x, s2p[t][4]);
                    fma2(tsb, u2.y, s2p[t][5]);
                    ull ts = add2(tsa, tsb);
                    ull tca = mul2(u0.x, c2p[t][0]);
                    fma2(tca, u0.y, c2p[t][1]);
                    fma2(tca, u1.x, c2p[t][2]);
                    ull tcb = mul2(u1.y, c2p[t][3]);
                    fma2(tcb, u2.x, c2p[t][4]);
                    fma2(tcb, u2.y, c2p[t][5]);
                    ull tc = add2(tca, tcb);
                    ull ds1 = pack2(s1[t][j], s1[t][j]);
                    ull dc1 = pack2(c1[t][j], c1[t][j]);
                    if (j == 0) {
                        uss[t] = mul2(ts, ds1);
                        ucs[t] = mul2(ts, dc1);
                        usc[t] = mul2(tc, ds1);
                    } else {
                        fma2(uss[t], ts, ds1);
                        fma2(ucs[t], ts, dc1);
                        fma2(usc[t], tc, ds1);
                    }
                }
            }
            #pragma unroll
            for (int t = 0; t < 2; ++t) {
                float us = hadd2(uss[t]), uc = hadd2(ucs[t]), uq = hadd2(usc[t]);
                gf[t][d] = fmaf(us, s0v[t], gf[t][d]);
                dA[t][d] = fmaf(us, c0v[t], dA[t][d]);
                dB[t][d] = fmaf(uc, s0v[t], dB[t][d]);
                dC[t][d] = fmaf(uq, s0v[t], dC[t][d]);
            }
        }
    }

    // ---- per-lane projection to h[3] (linear in dA/dB/dC) ----
    float hv[2][3];
    #pragma unroll
    for (int t = 0; t < 2; ++t) {
        float vx = ve[t][0], vy = ve[t][1], vz = ve[t][2];
        float F0 = vx * dA[t][0] + vy * dB[t][0] + vz * dC[t][0];
        float F1 = vx * dA[t][1] + vy * dB[t][1] + vz * dC[t][1];
        float F2 = vx * dA[t][2] + vy * dB[t][2] + vz * dC[t][2];
        float F3 = vx * dA[t][3] + vy * dB[t][3] + vz * dC[t][3];
        float F4 = vx * dA[t][4] + vy * dB[t][4] + vz * dC[t][4];
        float F5 = vx * dA[t][5] + vy * dB[t][5] + vz * dC[t][5];
        float A0 = vx * F0 + vy * F1 + vz * F3;
        float A1 = vx * F1 + vy * F2 + vz * F4;
        float A2 = vx * F3 + vy * F4 + vz * F5;
        float xx = vx * vx, yy = vy * vy, zz = vz * vz;
        float xy = 2.f * vx * vy, xz = 2.f * vx * vz, yz = 2.f * vy * vz;
        float B0 = xx * dA[t][0] + yy * dA[t][2] + zz * dA[t][5] + xy * dA[t][1] + xz * dA[t][3] + yz * dA[t][4];
        float B1 = xx * dB[t][0] + yy * dB[t][2] + zz * dB[t][5] + xy * dB[t][1] + xz * dB[t][3] + yz * dB[t][4];
        float B2 = xx * dC[t][0] + yy * dC[t][2] + zz * dC[t][5] + xy * dC[t][1] + xz * dC[t][3] + yz * dC[t][4];
        hv[t][0] = 2.f * A0 - B0;
        hv[t][1] = 2.f * A1 - B1;
        hv[t][2] = 2.f * A2 - B2;
    }

    // ---- reduce 9 values per trajectory across the 8-lane group (masked) ----
    #pragma unroll
    for (int t = 0; t < 2; ++t)
        #pragma unroll
        for (int o = 1; o <= 4; o <<= 1) {
            #pragma unroll
            for (int d = 0; d < 6; ++d)
                gf[t][d] += __shfl_xor_sync(gmask, gf[t][d], o);
            #pragma unroll
            for (int c = 0; c < 3; ++c)
                hv[t][c] += __shfl_xor_sync(gmask, hv[t][c], o);
        }

    #pragma unroll
    for (int t = 0; t < 2; ++t) {
        float g00 = gf[t][0] + 1.f, g01 = gf[t][1], g11 = gf[t][2] + 1.f;
        float g02 = gf[t][3], g12 = gf[t][4], g22 = gf[t][5] + 1.f;
        float k00 = g11 * g22 - g12 * g12;
        float k01 = g02 * g12 - g01 * g22;
        float k02 = g01 * g12 - g02 * g11;
        float det = g00 * k00 + g01 * k01 + g02 * k02;
        float idet = 1.0f / det;
        float i00 = k00 * idet, i01 = k01 * idet, i02 = k02 * idet;
        float i11 = (g00 * g22 - g02 * g02) * idet;
        float i12 = (g01 * g02 - g00 * g12) * idet;
        float i22 = (g00 * g11 - g01 * g01) * idet;
        float h0 = hv[t][0], h1 = hv[t][1], h2 = hv[t][2];
        ac[t][0] = -0.5f * (i00 * h0 + i01 * h1 + i02 * h2);
        ac[t][1] = -0.5f * (i01 * h0 + i11 * h1 + i12 * h2);
        ac[t][2] = -0.5f * (i02 * h0 + i12 * h1 + i22 * h2);
    }
}

// ---------------------------------------------------------------------------
// Fused kernel: per-block prep (L, W into padded smem) + RK4 for 2 traj/group.
// 296 blocks x 128 threads; groups strided across blocks for SM balance:
// group = blockIdx.x + 296 * slot  (slot = tid/8). ~13.8 active groups/block.
// ---------------------------------------------------------------------------
__global__ void __launch_bounds__(128)
geo_kernel(const float* __restrict__ pos0, const float* __restrict__ vel0,
           const float* __restrict__ beta, const float* __restrict__ ls,
           const float* __restrict__ basis, float* __restrict__ out)
{
    extern __shared__ ulonglong2 Wd[];
    __shared__ float sprm[9];
    __shared__ float red[12];

    int tid = threadIdx.x;

    // ---- L = 1.5 * max|basis| per dim ----
    {
        float m0 = 0.f, m1 = 0.f, m2 = 0.f;
        for (int r = tid; r < 256; r += 128) {
            m0 = fmaxf(m0, fabsf(basis[r * 3 + 0]));
            m1 = fmaxf(m1, fabsf(basis[r * 3 + 1]));
            m2 = fmaxf(m2, fabsf(basis[r * 3 + 2]));
        }
        #pragma unroll
        for (int o = 16; o > 0; o >>= 1) {
            m0 = fmaxf(m0, __shfl_xor_sync(0xffffffffu, m0, o));
            m1 = fmaxf(m1, __shfl_xor_sync(0xffffffffu, m1, o));
            m2 = fmaxf(m2, __shfl_xor_sync(0xffffffffu, m2, o));
        }
        if ((tid & 31) == 0) {
            int w = tid >> 5;
            red[w * 3 + 0] = m0; red[w * 3 + 1] = m1; red[w * 3 + 2] = m2;
        }
        __syncthreads();
        if (tid == 0) {
            #pragma unroll
            for (int d = 0; d < 3; ++d) {
                float M = fmaxf(fmaxf(red[d], red[3 + d]), fmaxf(red[6 + d], red[9 + d]));
                float L = 1.5f * M;
                sprm[d]     = L;
                sprm[3 + d] = (float)(PI_D) / (2.0f * L);
                sprm[6 + d] = 1.0f / sqrtf(L);
            }
        }
        __syncthreads();
    }
    float L0 = sprm[0], L1 = sprm[1], L2 = sprm[2];
    float w10 = sprm[3], w11 = sprm[4], w12 = sprm[5];
    float is0 = sprm[6], is1 = sprm[7], is2 = sprm[8];

    // ---- W into padded smem layout (precise math: W feeds everything) ----
    {
        float* Wf = (float*)Wd;
        for (int idx = tid; idx < 10368; idx += 128) {
            int i2 = idx % 12;
            int d  = (idx / 12) % 6;
            int i1 = (idx / 72) % 12;
            int i0 = idx / 864;
            int m  = (i0 * 12 + i1) * 12 + i2;
            float ls0 = ls[d * 3 + 0], ls1 = ls[d * 3 + 1], ls2 = ls[d * 3 + 2];
            float q0 = w10 * (float)(i0 + 1);
            float q1 = w11 * (float)(i1 + 1);
            float q2 = w12 * (float)(i2 + 1);
            float e = -0.25f * (q0 * q0 * ls0 * ls0 + q1 * q1 * ls1 * ls1 + q2 * q2 * ls2 * ls2);
            float psd = 3.96850262992049984f * sqrtf(ls0 * ls1 * ls2) * expf(e);
            Wf[i0 * 868 + i1 * 72 + d * 12 + i2] = beta[d * 1728 + m] * psd;
        }
    }
    __syncthreads();

    // ---- integrate: 2 trajectories per 8-lane group, strided group ids ----
    int slot  = tid >> 3;
    int sub   = tid & 7;
    int group = blockIdx.x + NBLK * slot;
    if (group >= NGROUP) return;          // idle slots: no barriers below

    unsigned gmask = 0xFFu << ((tid & 31) & ~7);   // this 8-lane group's lanes

    int i0b = (sub >> 1) * 3;
    int i1b = (sub & 1) * 6;

    float p[2][3], v[2][3];
    #pragma unroll
    for (int t = 0; t < 2; ++t) {
        int b = group * 2 + t;
        p[t][0] = pos0[b * 3 + 0]; p[t][1] = pos0[b * 3 + 1]; p[t][2] = pos0[b * 3 + 2];
        v[t][0] = vel0[b * 3 + 0]; v[t][1] = vel0[b * 3 + 1]; v[t][2] = vel0[b * 3 + 2];
    }

    if (sub == 0) {
        #pragma unroll
        for (int t = 0; t < 2; ++t) {
            int b = group * 2 + t;
            float* op = out + (size_t)0 * NB * 3 + b * 3;
            float* ov = out + (size_t)1 * NB * 3 + b * 3;
            op[0] = p[t][0]; op[1] = p[t][1]; op[2] = p[t][2];
            ov[0] = v[t][0]; ov[1] = v[t][1]; ov[2] = v[t][2];
        }
    }

    const float dt  = (float)(1.0 / 49.0);
    const float hdt = (float)(0.5 * (1.0 / 49.0));
    const float dt6 = (float)((1.0 / 49.0) / 6.0);

    #pragma unroll 1
    for (int ts = 1; ts < TSTEPS; ++ts) {
        float pac[2][3], vac[2][3], dp[2][3], dv[2][3];
        #pragma unroll
        for (int t = 0; t < 2; ++t)
            #pragma unroll
            for (int c = 0; c < 3; ++c) {
                pac[t][c] = 0.f; vac[t][c] = 0.f; dp[t][c] = 0.f; dv[t][c] = 0.f;
            }
        #pragma unroll 1
        for (int s = 0; s < 4; ++s) {
            float pe[2][3], ve[2][3], ac[2][3];
            float cs = (s == 3) ? dt : hdt;
            #pragma unroll
            for (int t = 0; t < 2; ++t)
                #pragma unroll
                for (int c = 0; c < 3; ++c) {
                    if (s == 0) { pe[t][c] = p[t][c]; ve[t][c] = v[t][c]; }
                    else {
                        pe[t][c] = fmaf(cs, dp[t][c], p[t][c]);
                        ve[t][c] = fmaf(cs, dv[t][c], v[t][c]);
                    }
                }
            accel2(Wd, i0b, i1b, gmask, L0, L1, L2, w10, w11, w12, is0, is1, is2,
                   pe, ve, ac);
            float w = (s == 0 || s == 3) ? 1.f : 2.f;
            #pragma unroll
            for (int t = 0; t < 2; ++t)
                #pragma unroll
                for (int c = 0; c < 3; ++c) {
                    dp[t][c] = ve[t][c]; dv[t][c] = ac[t][c];
                    pac[t][c] = fmaf(w, dp[t][c], pac[t][c]);
                    vac[t][c] = fmaf(w, dv[t][c], vac[t][c]);
                }
        }
        #pragma unroll
        for (int t = 0; t < 2; ++t)
            #pragma unroll
            for (int c = 0; c < 3; ++c) {
                p[t][c] = fmaf(dt6, pac[t][c], p[t][c]);
                v[t][c] = fmaf(dt6, vac[t][c], v[t][c]);
            }

        if (sub == 0) {
            #pragma unroll
            for (int t = 0; t < 2; ++t) {
                int b = group * 2 + t;
                float* op = out + ((size_t)(ts * 2 + 0) * NB + b) * 3;
                float* ov = out + ((size_t)(ts * 2 + 1) * NB + b) * 3;
                op[0] = p[t][0]; op[1] = p[t][1]; op[2] = p[t][2];
                ov[0] = v[t][0]; ov[1] = v[t][1]; ov[2] = v[t][2];
            }
        }
    }
}

// ---------------------------------------------------------------------------
extern "C" void kernel_launch(void* const* d_in, const int* in_sizes, int n_in,
                              void* d_out, int out_size) {
    const float* pos0  = (const float*)d_in[0];
    const float* vel0  = (const float*)d_in[1];
    const float* beta  = (const float*)d_in[2];
    const float* ls    = (const float*)d_in[3];
    const float* basis = (const float*)d_in[4];
    float* out = (float*)d_out;

    geo_kernel<<<NBLK, 128, W_FLOATS * 4>>>(pos0, vel0, beta, ls, basis, out);
}